// round 2
// baseline (speedup 1.0000x reference)
#include <cuda_runtime.h>
#include <cstdint>

#define DIMC   384
#define NH     12
#define HD     32
#define NTOK   49
#define BWIN   4096
#define NWIN   64
#define M_TOTAL (BWIN*NTOK)          // 200704
#define S3      77070336             // 4096*12*49*32  (one of q/k/v)

// Scratch (allocation-free rule: __device__ globals)
__device__ float g_qkv[3 * S3];      // q | k | v, each [b,h,n,d]
__device__ float g_att[S3];          // attention output [b,n,384]

typedef unsigned long long ull;

__device__ __forceinline__ ull pk2(float x, float y) {
    ull r; asm("mov.b64 %0,{%1,%2};" : "=l"(r) : "f"(x), "f"(y)); return r;
}
__device__ __forceinline__ void up2(ull v, float& x, float& y) {
    asm("mov.b64 {%0,%1},%2;" : "=f"(x), "=f"(y) : "l"(v));
}
__device__ __forceinline__ ull fma2(ull a, ull b, ull c) {
    ull d; asm("fma.rn.f32x2 %0,%1,%2,%3;" : "=l"(d) : "l"(a), "l"(b), "l"(c)); return d;
}

// ============================================================================
// GEMM: C[M,N] = A[M,K] * B[N,K]^T + bias, K=384.
// BM=BN=64, BK=16, 256 threads, 4x4 microtile with packed f32x2 FMAs.
// MODE 0: A = x, writes g_qkv with [s,b,h,n,d] permute + q scaling.
// MODE 1: A = g_att, writes C (d_out) row-major [M, NCOLS].
// Grid: (N/64, M/64) -- N fastest so consecutive blocks reuse the same A tile.
// ============================================================================
template<int MODE, int NCOLS>
__global__ void __launch_bounds__(256)
gemm64(const float* __restrict__ A, const float* __restrict__ B,
       const float* __restrict__ bias, float* __restrict__ C)
{
    __shared__ float As[16][68];
    __shared__ float Bs[16][68];
    const int K = DIMC;
    const float* Ap = (MODE == 0) ? A : (const float*)g_att;

    int bn = blockIdx.x * 64;
    int bm = blockIdx.y * 64;
    int t  = threadIdx.x;
    int tx = t & 15, ty = t >> 4;
    int lrow = t >> 2, lk = (t & 3) << 2;

    const float* ga = Ap + (size_t)(bm + lrow) * K + lk;
    const float* gb = B  + (size_t)(bn + lrow) * K + lk;

    ull acc[4][2];
    #pragma unroll
    for (int i = 0; i < 4; i++) { acc[i][0] = 0ull; acc[i][1] = 0ull; }

    for (int kt = 0; kt < K; kt += 16) {
        float4 av = *(const float4*)(ga + kt);
        float4 bv = *(const float4*)(gb + kt);
        As[lk+0][lrow] = av.x; As[lk+1][lrow] = av.y;
        As[lk+2][lrow] = av.z; As[lk+3][lrow] = av.w;
        Bs[lk+0][lrow] = bv.x; Bs[lk+1][lrow] = bv.y;
        Bs[lk+2][lrow] = bv.z; Bs[lk+3][lrow] = bv.w;
        __syncthreads();
        #pragma unroll
        for (int k = 0; k < 16; k++) {
            float4 a = *(const float4*)&As[k][ty << 2];
            float4 b = *(const float4*)&Bs[k][tx << 2];
            ull b01 = pk2(b.x, b.y), b23 = pk2(b.z, b.w);
            ull a0 = pk2(a.x, a.x), a1 = pk2(a.y, a.y);
            ull a2 = pk2(a.z, a.z), a3 = pk2(a.w, a.w);
            acc[0][0] = fma2(a0, b01, acc[0][0]); acc[0][1] = fma2(a0, b23, acc[0][1]);
            acc[1][0] = fma2(a1, b01, acc[1][0]); acc[1][1] = fma2(a1, b23, acc[1][1]);
            acc[2][0] = fma2(a2, b01, acc[2][0]); acc[2][1] = fma2(a2, b23, acc[2][1]);
            acc[3][0] = fma2(a3, b01, acc[3][0]); acc[3][1] = fma2(a3, b23, acc[3][1]);
        }
        __syncthreads();
    }

    float c[4][4];
    #pragma unroll
    for (int i = 0; i < 4; i++) {
        up2(acc[i][0], c[i][0], c[i][1]);
        up2(acc[i][1], c[i][2], c[i][3]);
    }

    int gj = bn + (tx << 2);
    float4 bb = *(const float4*)(bias + gj);

    if (MODE == 1) {
        #pragma unroll
        for (int i = 0; i < 4; i++) {
            int gi = bm + (ty << 2) + i;
            float4 o = make_float4(c[i][0] + bb.x, c[i][1] + bb.y,
                                   c[i][2] + bb.z, c[i][3] + bb.w);
            *(float4*)(C + (size_t)gi * NCOLS + gj) = o;
        }
    } else {
        // gj in [0,1152): s = gj/384 (constant per block since 384 % 64 == 0)
        int s = gj / DIMC;
        int rem = gj - s * DIMC;
        int h = rem >> 5, d = rem & 31;
        float scl = (s == 0) ? 0.17677669529663687f : 1.0f;  // hd^-0.5 on q
        #pragma unroll
        for (int i = 0; i < 4; i++) {
            int gi = bm + (ty << 2) + i;
            int b = gi / NTOK;
            int n = gi - b * NTOK;
            float4 o = make_float4((c[i][0] + bb.x) * scl, (c[i][1] + bb.y) * scl,
                                   (c[i][2] + bb.z) * scl, (c[i][3] + bb.w) * scl);
            size_t dst = (size_t)s * S3 + (((size_t)b * NH + h) * NTOK + n) * HD + d;
            *(float4*)(g_qkv + dst) = o;
        }
    }
}

// ============================================================================
// Fused attention: one block per (window b, head h). 192 threads.
// S = q k^T (q pre-scaled) + rel-pos-bias + shifted-window mask, softmax, P V.
// q,k staged TRANSPOSED in smem -> outer-product formulation (f32x2 FMAs,
// conflict-free float4 smem reads).
// ============================================================================
__global__ void __launch_bounds__(192)
attn_kernel(const float* __restrict__ mask, const float* __restrict__ rpb,
            const int* __restrict__ relidx)
{
    __shared__ float qT[32][52];
    __shared__ float kT[32][52];
    __shared__ float vS[49][32];
    __shared__ float S[52][52];
    __shared__ float biasS[169];
    __shared__ unsigned char ridxS[2401];

    int bh = blockIdx.x;
    int b  = bh / NH;
    int h  = bh - b * NH;
    int w  = b & (NWIN - 1);       // shifted-window mask index
    int t  = threadIdx.x;

    const float* qg = g_qkv + (size_t)bh * (NTOK * HD);
    const float* kg = qg + S3;
    const float* vg = qg + 2 * (size_t)S3;

    for (int i = t; i < NTOK * HD; i += 192) {
        int n = i >> 5, j = i & 31;
        qT[j][n] = qg[i];
        kT[j][n] = kg[i];
        vS[n][j] = vg[i];
    }
    if (t < 96) {                   // zero the n/m padding columns 49..51
        int j = t / 3, cp = 49 + (t % 3);
        qT[j][cp] = 0.f; kT[j][cp] = 0.f;
    }
    for (int i = t; i < 169; i += 192) biasS[i] = rpb[i * NH + h];
    for (int i = t; i < 2401; i += 192) ridxS[i] = (unsigned char)relidx[i];
    __syncthreads();

    // ---- S = q k^T : 13x13 groups of 4x4 tiles, threads 0..168 ----
    if (t < 169) {
        int n0 = (t / 13) << 2, m0 = (t % 13) << 2;
        ull acc[4][2];
        #pragma unroll
        for (int i = 0; i < 4; i++) { acc[i][0] = 0ull; acc[i][1] = 0ull; }
        #pragma unroll
        for (int j = 0; j < 32; j++) {
            float4 a = *(const float4*)&qT[j][n0];
            float4 k4 = *(const float4*)&kT[j][m0];
            ull b01 = pk2(k4.x, k4.y), b23 = pk2(k4.z, k4.w);
            ull a0 = pk2(a.x, a.x), a1 = pk2(a.y, a.y);
            ull a2 = pk2(a.z, a.z), a3 = pk2(a.w, a.w);
            acc[0][0] = fma2(a0, b01, acc[0][0]); acc[0][1] = fma2(a0, b23, acc[0][1]);
            acc[1][0] = fma2(a1, b01, acc[1][0]); acc[1][1] = fma2(a1, b23, acc[1][1]);
            acc[2][0] = fma2(a2, b01, acc[2][0]); acc[2][1] = fma2(a2, b23, acc[2][1]);
            acc[3][0] = fma2(a3, b01, acc[3][0]); acc[3][1] = fma2(a3, b23, acc[3][1]);
        }
        const float* mrow = mask + (size_t)w * (NTOK * NTOK);
        #pragma unroll
        for (int i = 0; i < 4; i++) {
            float cc[4];
            up2(acc[i][0], cc[0], cc[1]);
            up2(acc[i][1], cc[2], cc[3]);
            int n = n0 + i;
            #pragma unroll
            for (int j2 = 0; j2 < 4; j2++) {
                int m = m0 + j2;
                float val;
                if (m < NTOK && n < NTOK)
                    val = cc[j2] + biasS[ridxS[n * NTOK + m]] + mrow[n * NTOK + m];
                else
                    val = -1e30f;
                S[n][m] = val;
            }
        }
    }
    __syncthreads();

    // ---- softmax over m, one thread per row ----
    if (t < NTOK) {
        float mx = -1e30f;
        for (int m = 0; m < NTOK; m++) mx = fmaxf(mx, S[t][m]);
        float sum = 0.f;
        for (int m = 0; m < NTOK; m++) {
            float e = __expf(S[t][m] - mx);
            S[t][m] = e;
            sum += e;
        }
        float inv = 1.0f / sum;
        for (int m = 0; m < NTOK; m++) S[t][m] *= inv;
    }
    __syncthreads();

    // ---- out = P V : 13 n-groups x 8 d-groups, threads 0..103 ----
    if (t < 104) {
        int n0 = (t >> 3) << 2, d0 = (t & 7) << 2;
        ull acc[4][2];
        #pragma unroll
        for (int i = 0; i < 4; i++) { acc[i][0] = 0ull; acc[i][1] = 0ull; }
        for (int m = 0; m < NTOK; m++) {
            float4 vv = *(const float4*)&vS[m][d0];
            ull v01 = pk2(vv.x, vv.y), v23 = pk2(vv.z, vv.w);
            #pragma unroll
            for (int i = 0; i < 4; i++) {
                float p = S[n0 + i][m];
                ull pp = pk2(p, p);
                acc[i][0] = fma2(pp, v01, acc[i][0]);
                acc[i][1] = fma2(pp, v23, acc[i][1]);
            }
        }
        size_t obase = ((size_t)b * NTOK) * DIMC + h * HD + d0;
        #pragma unroll
        for (int i = 0; i < 4; i++) {
            int n = n0 + i;
            if (n < NTOK) {
                float o0, o1, o2, o3;
                up2(acc[i][0], o0, o1);
                up2(acc[i][1], o2, o3);
                *(float4*)(g_att + obase + (size_t)n * DIMC) = make_float4(o0, o1, o2, o3);
            }
        }
    }
}

// ============================================================================
// Launch
// ============================================================================
extern "C" void kernel_launch(void* const* d_in, const int* in_sizes, int n_in,
                              void* d_out, int out_size)
{
    const float* x      = (const float*)d_in[0];
    const float* mask   = (const float*)d_in[1];
    const float* qkv_w  = (const float*)d_in[2];
    const float* qkv_b  = (const float*)d_in[3];
    const float* proj_w = (const float*)d_in[4];
    const float* proj_b = (const float*)d_in[5];
    const float* rpb    = (const float*)d_in[6];
    const int*   relidx = (const int*)d_in[7];
    float* out = (float*)d_out;

    (void)in_sizes; (void)n_in; (void)out_size;

    // 1) QKV projection + permute + q-scale
    gemm64<0, 1152><<<dim3(1152 / 64, M_TOTAL / 64), 256>>>(x, qkv_w, qkv_b, nullptr);
    // 2) Windowed attention (bias + mask + softmax fused)
    attn_kernel<<<BWIN * NH, 192>>>(mask, rpb, relidx);
    // 3) Output projection
    gemm64<1, 384><<<dim3(384 / 64, M_TOTAL / 64), 256>>>(nullptr, proj_w, proj_b, out);
}

// round 4
// speedup vs baseline: 2.3912x; 2.3912x over previous
#include <cuda_runtime.h>
#include <cuda_fp16.h>
#include <cstdint>

#define DIMC   384
#define NH     12
#define HD     32
#define NTOK   49
#define BWIN   4096
#define NWIN   64
#define M_TOTAL (BWIN*NTOK)          // 200704
#define S3      77070336             // 4096*12*49*32  (one of q/k/v)

// ---------------- scratch (__device__ globals; no allocs allowed) -----------
__device__ __align__(16) float  g_qkv[3 * S3];               // q|k|v [s][b,h,n,d]
__device__ __align__(16) float  g_att[S3];                   // attn out [b,n,384]
__device__ __align__(16) __half g_ah[(size_t)M_TOTAL * 384]; // activations fp16 hi
__device__ __align__(16) __half g_wq2[1152 * 768];           // qkv_w  (hi|lo)
__device__ __align__(16) __half g_wp2[384 * 768];            // proj_w (hi|lo)

typedef unsigned long long ull;

__device__ __forceinline__ uint32_t smem_u32(const void* p) {
    uint32_t a;
    asm("{ .reg .u64 t; cvta.to.shared.u64 t, %1; cvt.u32.u64 %0, t; }"
        : "=r"(a) : "l"(p));
    return a;
}

#define CP_ASYNC16(dst, src) \
    asm volatile("cp.async.cg.shared.global [%0], [%1], 16;" :: "r"(dst), "l"(src))
#define CP_COMMIT()  asm volatile("cp.async.commit_group;" ::: "memory")
#define CP_WAIT(n)   asm volatile("cp.async.wait_group %0;" :: "n"(n) : "memory")

#define LDSM4(r, addr) \
    asm volatile("ldmatrix.sync.aligned.m8n8.x4.shared.b16 {%0,%1,%2,%3}, [%4];" \
        : "=r"((r)[0]), "=r"((r)[1]), "=r"((r)[2]), "=r"((r)[3]) : "r"(addr))

#define MMA16816(c, a, bb0, bb1) \
    asm volatile("mma.sync.aligned.m16n8k16.row.col.f32.f16.f16.f32 " \
        "{%0,%1,%2,%3}, {%4,%5,%6,%7}, {%8,%9}, {%0,%1,%2,%3};" \
        : "+f"((c)[0]), "+f"((c)[1]), "+f"((c)[2]), "+f"((c)[3]) \
        : "r"((a)[0]), "r"((a)[1]), "r"((a)[2]), "r"((a)[3]), "r"(bb0), "r"(bb1))

// ---------------- fp32 -> fp16 converters ----------------------------------
// activations: hi plane only. USE_ATT=1 reads g_att.
template<int USE_ATT>
__global__ void __launch_bounds__(256)
act_split(const float* __restrict__ src)
{
    size_t i = ((size_t)blockIdx.x * 256 + threadIdx.x) * 8;
    const float* s = USE_ATT ? (const float*)g_att : src;
    float4 v0 = *(const float4*)(s + i);
    float4 v1 = *(const float4*)(s + i + 4);
    __half2 h0 = __floats2half2_rn(v0.x, v0.y);
    __half2 h1 = __floats2half2_rn(v0.z, v0.w);
    __half2 h2 = __floats2half2_rn(v1.x, v1.y);
    __half2 h3 = __floats2half2_rn(v1.z, v1.w);
    uint4 o;
    o.x = *(uint32_t*)&h0; o.y = *(uint32_t*)&h1;
    o.z = *(uint32_t*)&h2; o.w = *(uint32_t*)&h3;
    *(uint4*)(g_ah + i) = o;
}

// weights: (hi | lo) planes, row stride 768 halves. W: 1 = qkv_w, 2 = proj_w
template<int W>
__global__ void __launch_bounds__(256)
w_split(const float* __restrict__ w, int total4)
{
    int i = blockIdx.x * 256 + threadIdx.x;
    if (i >= total4) return;
    __half* dst = (W == 1) ? g_wq2 : g_wp2;
    int e = i << 2;
    int r = e / DIMC, k = e - r * DIMC;
    float4 v = *(const float4*)(w + e);
    float f[4] = {v.x, v.y, v.z, v.w};
    __half hi[4], lo[4];
    #pragma unroll
    for (int q = 0; q < 4; q++) {
        hi[q] = __float2half_rn(f[q]);
        lo[q] = __float2half_rn(f[q] - __half2float(hi[q]));
    }
    __half2 hh0 = __halves2half2(hi[0], hi[1]);
    __half2 hh1 = __halves2half2(hi[2], hi[3]);
    __half2 ll0 = __halves2half2(lo[0], lo[1]);
    __half2 ll1 = __halves2half2(lo[2], lo[3]);
    size_t ro = (size_t)r * 768 + k;
    *(uint2*)(dst + ro)       = make_uint2(*(uint32_t*)&hh0, *(uint32_t*)&hh1);
    *(uint2*)(dst + ro + 384) = make_uint2(*(uint32_t*)&ll0, *(uint32_t*)&ll1);
}

// ---------------- HMMA GEMM: C[M,N] = Ah[M,384] * W2[N,768]^T --------------
// Keff = 768: chunks 0-5 use W hi planes, 6-11 lo planes; A chunk = c % 6.
// BM=128, BN=128, BK=64 (128B rows, xor swizzle), 4-stage cp.async pipeline.
// 8 warps (4 along M x 2 along N), warp tile 32x64, m16n8k16 fragments.
#define STAGEB 32768
#define CHUNKS 12
#define SMEM_DYN (4 * STAGEB)

// MODE 0: QKV -> g_qkv with bias + q-scale + [s,b,h,n,d] permute
// MODE 1: proj -> C row-major [M,384] + bias
template<int MODE>
__global__ void __launch_bounds__(256)
mma_gemm(const float* __restrict__ bias, float* __restrict__ C)
{
    extern __shared__ __align__(128) char smem[];
    const uint32_t sbase = smem_u32(smem);
    const int t    = threadIdx.x;
    const int wid  = t >> 5, lane = t & 31;
    const int bn   = blockIdx.x * 128;
    const int bm   = blockIdx.y * 128;

    const char* Ab = (const char*)g_ah + (size_t)bm * 768;
    const char* Bb = (const char*)((MODE == 0) ? g_wq2 : g_wp2) + (size_t)bn * 1536;

    auto load = [&](int c) {
        const int st = c & 3;
        const uint32_t sA = sbase + st * STAGEB;
        const uint32_t sB = sA + 16384;
        const int ao = (c % 6) * 128;
        const int bo = c * 128;
        #pragma unroll
        for (int i = 0; i < 4; i++) {
            int idx = t + i * 256;
            int r = idx >> 3, sg = idx & 7;
            CP_ASYNC16(sA + r * 128 + ((sg ^ (r & 7)) << 4),
                       Ab + (size_t)r * 768 + ao + sg * 16);
        }
        #pragma unroll
        for (int i = 0; i < 4; i++) {
            int idx = t + i * 256;
            int r = idx >> 3, sg = idx & 7;
            CP_ASYNC16(sB + r * 128 + ((sg ^ (r & 7)) << 4),
                       Bb + (size_t)r * 1536 + bo + sg * 16);
        }
    };

    float acc[2][8][4];
    #pragma unroll
    for (int m = 0; m < 2; m++)
        #pragma unroll
        for (int n = 0; n < 8; n++)
            #pragma unroll
            for (int q = 0; q < 4; q++) acc[m][n][q] = 0.f;

    load(0); CP_COMMIT();
    load(1); CP_COMMIT();
    load(2); CP_COMMIT();

    const int wm = wid & 3, wn = wid >> 2;
    const int lrow = lane & 15, lkh = lane >> 4;
    const int lx = lrow & 7;               // row-dependent part of swizzle
    const int ar0 = wm * 32 + lrow, ar1 = ar0 + 16;
    const int br0 = wn * 64 + lrow;

    for (int j = 0; j < CHUNKS; j++) {
        CP_WAIT(2);
        __syncthreads();
        if (j + 3 < CHUNKS) load(j + 3);
        CP_COMMIT();

        const uint32_t sA = sbase + (j & 3) * STAGEB;
        const uint32_t sB = sA + 16384;
        #pragma unroll
        for (int ks = 0; ks < 4; ks++) {
            const int kx = (((ks << 1) | lkh) ^ lx) << 4;
            uint32_t a0[4], a1[4], b0[4], b1[4], b2[4], b3[4];
            LDSM4(a0, sA + ar0 * 128 + kx);
            LDSM4(a1, sA + ar1 * 128 + kx);
            LDSM4(b0, sB + (br0     ) * 128 + kx);
            LDSM4(b1, sB + (br0 + 16) * 128 + kx);
            LDSM4(b2, sB + (br0 + 32) * 128 + kx);
            LDSM4(b3, sB + (br0 + 48) * 128 + kx);
            MMA16816(acc[0][0], a0, b0[0], b0[2]);
            MMA16816(acc[0][1], a0, b0[1], b0[3]);
            MMA16816(acc[0][2], a0, b1[0], b1[2]);
            MMA16816(acc[0][3], a0, b1[1], b1[3]);
            MMA16816(acc[0][4], a0, b2[0], b2[2]);
            MMA16816(acc[0][5], a0, b2[1], b2[3]);
            MMA16816(acc[0][6], a0, b3[0], b3[2]);
            MMA16816(acc[0][7], a0, b3[1], b3[3]);
            MMA16816(acc[1][0], a1, b0[0], b0[2]);
            MMA16816(acc[1][1], a1, b0[1], b0[3]);
            MMA16816(acc[1][2], a1, b1[0], b1[2]);
            MMA16816(acc[1][3], a1, b1[1], b1[3]);
            MMA16816(acc[1][4], a1, b2[0], b2[2]);
            MMA16816(acc[1][5], a1, b2[1], b2[3]);
            MMA16816(acc[1][6], a1, b3[0], b3[2]);
            MMA16816(acc[1][7], a1, b3[1], b3[3]);
        }
    }

    // ---- epilogue: C frag thread map: rows +tq (+8), cols +tr*2 ----
    const int tq = lane >> 2, tr = lane & 3;
    if (MODE == 0) {
        const int s = bn / DIMC;                 // BN=128, 384%128==0 -> const
        const float scl = (s == 0) ? 0.17677669529663687f : 1.0f;
        #pragma unroll
        for (int mt = 0; mt < 2; mt++) {
            const int rb = bm + wm * 32 + mt * 16 + tq;
            #pragma unroll
            for (int pr = 0; pr < 2; pr++) {
                const int gi = rb + pr * 8;
                const int b = gi / NTOK, n = gi - b * NTOK;
                #pragma unroll
                for (int nt = 0; nt < 8; nt++) {
                    const int gj = bn + wn * 64 + nt * 8 + tr * 2;
                    const int h = (gj - s * DIMC) >> 5, d = gj & 31;
                    float2 bb = *(const float2*)(bias + gj);
                    float2 o;
                    o.x = (acc[mt][nt][pr * 2 + 0] + bb.x) * scl;
                    o.y = (acc[mt][nt][pr * 2 + 1] + bb.y) * scl;
                    *(float2*)(g_qkv + (size_t)s * S3 +
                               (((size_t)b * NH + h) * NTOK + n) * HD + d) = o;
                }
            }
        }
    } else {
        #pragma unroll
        for (int mt = 0; mt < 2; mt++) {
            const int rb = bm + wm * 32 + mt * 16 + tq;
            #pragma unroll
            for (int pr = 0; pr < 2; pr++) {
                const int gi = rb + pr * 8;
                #pragma unroll
                for (int nt = 0; nt < 8; nt++) {
                    const int gj = bn + wn * 64 + nt * 8 + tr * 2;
                    float2 bb = *(const float2*)(bias + gj);
                    float2 o;
                    o.x = acc[mt][nt][pr * 2 + 0] + bb.x;
                    o.y = acc[mt][nt][pr * 2 + 1] + bb.y;
                    *(float2*)(C + (size_t)gi * DIMC + gj) = o;
                }
            }
        }
    }
}

// ---------------- fused window attention (R2, unchanged) -------------------
__device__ __forceinline__ ull pk2(float x, float y) {
    ull r; asm("mov.b64 %0,{%1,%2};" : "=l"(r) : "f"(x), "f"(y)); return r;
}
__device__ __forceinline__ void up2(ull v, float& x, float& y) {
    asm("mov.b64 {%0,%1},%2;" : "=f"(x), "=f"(y) : "l"(v));
}
__device__ __forceinline__ ull fma2(ull a, ull b, ull c) {
    ull d; asm("fma.rn.f32x2 %0,%1,%2,%3;" : "=l"(d) : "l"(a), "l"(b), "l"(c)); return d;
}

__global__ void __launch_bounds__(192)
attn_kernel(const float* __restrict__ mask, const float* __restrict__ rpb,
            const int* __restrict__ relidx)
{
    __shared__ float qT[32][52];
    __shared__ float kT[32][52];
    __shared__ float vS[49][32];
    __shared__ float S[52][52];
    __shared__ float biasS[169];
    __shared__ unsigned char ridxS[2401];

    int bh = blockIdx.x;
    int b  = bh / NH;
    int h  = bh - b * NH;
    int w  = b & (NWIN - 1);
    int t  = threadIdx.x;

    const float* qg = g_qkv + (size_t)bh * (NTOK * HD);
    const float* kg = qg + S3;
    const float* vg = qg + 2 * (size_t)S3;

    for (int i = t; i < NTOK * HD; i += 192) {
        int n = i >> 5, j = i & 31;
        qT[j][n] = qg[i];
        kT[j][n] = kg[i];
        vS[n][j] = vg[i];
    }
    if (t < 96) {
        int j = t / 3, cp = 49 + (t % 3);
        qT[j][cp] = 0.f; kT[j][cp] = 0.f;
    }
    for (int i = t; i < 169; i += 192) biasS[i] = rpb[i * NH + h];
    for (int i = t; i < 2401; i += 192) ridxS[i] = (unsigned char)relidx[i];
    __syncthreads();

    if (t < 169) {
        int n0 = (t / 13) << 2, m0 = (t % 13) << 2;
        ull a2c[4][2];
        #pragma unroll
        for (int i = 0; i < 4; i++) { a2c[i][0] = 0ull; a2c[i][1] = 0ull; }
        #pragma unroll
        for (int j = 0; j < 32; j++) {
            float4 a  = *(const float4*)&qT[j][n0];
            float4 k4 = *(const float4*)&kT[j][m0];
            ull b01 = pk2(k4.x, k4.y), b23 = pk2(k4.z, k4.w);
            ull a0 = pk2(a.x, a.x), a1 = pk2(a.y, a.y);
            ull a2 = pk2(a.z, a.z), a3 = pk2(a.w, a.w);
            a2c[0][0] = fma2(a0, b01, a2c[0][0]); a2c[0][1] = fma2(a0, b23, a2c[0][1]);
            a2c[1][0] = fma2(a1, b01, a2c[1][0]); a2c[1][1] = fma2(a1, b23, a2c[1][1]);
            a2c[2][0] = fma2(a2, b01, a2c[2][0]); a2c[2][1] = fma2(a2, b23, a2c[2][1]);
            a2c[3][0] = fma2(a3, b01, a2c[3][0]); a2c[3][1] = fma2(a3, b23, a2c[3][1]);
        }
        const float* mrow = mask + (size_t)w * (NTOK * NTOK);
        #pragma unroll
        for (int i = 0; i < 4; i++) {
            float cc[4];
            up2(a2c[i][0], cc[0], cc[1]);
            up2(a2c[i][1], cc[2], cc[3]);
            int n = n0 + i;
            #pragma unroll
            for (int j2 = 0; j2 < 4; j2++) {
                int m = m0 + j2;
                float val;
                if (m < NTOK && n < NTOK)
                    val = cc[j2] + biasS[ridxS[n * NTOK + m]] + mrow[n * NTOK + m];
                else
                    val = -1e30f;
                S[n][m] = val;
            }
        }
    }
    __syncthreads();

    if (t < NTOK) {
        float mx = -1e30f;
        for (int m = 0; m < NTOK; m++) mx = fmaxf(mx, S[t][m]);
        float sum = 0.f;
        for (int m = 0; m < NTOK; m++) {
            float e = __expf(S[t][m] - mx);
            S[t][m] = e;
            sum += e;
        }
        float inv = 1.0f / sum;
        for (int m = 0; m < NTOK; m++) S[t][m] *= inv;
    }
    __syncthreads();

    if (t < 104) {
        int n0 = (t >> 3) << 2, d0 = (t & 7) << 2;
        ull a2c[4][2];
        #pragma unroll
        for (int i = 0; i < 4; i++) { a2c[i][0] = 0ull; a2c[i][1] = 0ull; }
        for (int m = 0; m < NTOK; m++) {
            float4 vv = *(const float4*)&vS[m][d0];
            ull v01 = pk2(vv.x, vv.y), v23 = pk2(vv.z, vv.w);
            #pragma unroll
            for (int i = 0; i < 4; i++) {
                float p = S[n0 + i][m];
                ull pp = pk2(p, p);
                a2c[i][0] = fma2(pp, v01, a2c[i][0]);
                a2c[i][1] = fma2(pp, v23, a2c[i][1]);
            }
        }
        size_t obase = ((size_t)b * NTOK) * DIMC + h * HD + d0;
        #pragma unroll
        for (int i = 0; i < 4; i++) {
            int n = n0 + i;
            if (n < NTOK) {
                float o0, o1, o2, o3;
                up2(a2c[i][0], o0, o1);
                up2(a2c[i][1], o2, o3);
                *(float4*)(g_att + obase + (size_t)n * DIMC) = make_float4(o0, o1, o2, o3);
            }
        }
    }
}

// ---------------- launch ---------------------------------------------------
extern "C" void kernel_launch(void* const* d_in, const int* in_sizes, int n_in,
                              void* d_out, int out_size)
{
    const float* x      = (const float*)d_in[0];
    const float* mask   = (const float*)d_in[1];
    const float* qkv_w  = (const float*)d_in[2];
    const float* qkv_b  = (const float*)d_in[3];
    const float* proj_w = (const float*)d_in[4];
    const float* proj_b = (const float*)d_in[5];
    const float* rpb    = (const float*)d_in[6];
    const int*   relidx = (const int*)d_in[7];
    float* out = (float*)d_out;
    (void)in_sizes; (void)n_in; (void)out_size;

    cudaFuncSetAttribute(mma_gemm<0>, cudaFuncAttributeMaxDynamicSharedMemorySize, SMEM_DYN);
    cudaFuncSetAttribute(mma_gemm<1>, cudaFuncAttributeMaxDynamicSharedMemorySize, SMEM_DYN);

    const int actBlocks = (M_TOTAL * DIMC) / (256 * 8);   // 37632

    // 1) converters
    act_split<0><<<actBlocks, 256>>>(x);
    w_split<1><<<(1152 * 96 + 255) / 256, 256>>>(qkv_w, 1152 * 96);
    w_split<2><<<(384 * 96 + 255) / 256, 256>>>(proj_w, 384 * 96);

    // 2) QKV projection (HMMA) with fused bias + scale + permute
    mma_gemm<0><<<dim3(1152 / 128, M_TOTAL / 128), 256, SMEM_DYN>>>(qkv_b, nullptr);

    // 3) windowed attention (bias + mask + softmax fused)
    attn_kernel<<<BWIN * NH, 192>>>(mask, rpb, relidx);

    // 4) attention output -> fp16, then output projection (HMMA)
    act_split<1><<<actBlocks, 256>>>(nullptr);
    mma_gemm<1><<<dim3(DIMC / 128, M_TOTAL / 128), 256, SMEM_DYN>>>(proj_b, out);
}

// round 9
// speedup vs baseline: 3.0752x; 1.2861x over previous
#include <cuda_runtime.h>
#include <cuda_fp16.h>
#include <cstdint>

#define DIMC   384
#define NH     12
#define HD     32
#define NTOK   49
#define BWIN   4096
#define NWIN   64
#define M_TOTAL (BWIN*NTOK)          // 200704
#define S3      77070336             // 4096*12*49*32  (one of q/k/v)

// ---------------- scratch (__device__ globals; no allocs allowed) -----------
__device__ __align__(16) float  g_qkv[3 * S3];               // q|k|v [s][b,h,n,d]
__device__ __align__(16) __half g_ah[(size_t)M_TOTAL * 384]; // fp16 activations (x, then attn-out)
__device__ __align__(16) __half g_wq2[1152 * 768];           // qkv_w  (hi|lo)
__device__ __align__(16) __half g_wp2[384 * 768];            // proj_w (hi|lo)

typedef unsigned long long ull;

__device__ __forceinline__ uint32_t smem_u32(const void* p) {
    uint32_t a;
    asm("{ .reg .u64 t; cvta.to.shared.u64 t, %1; cvt.u32.u64 %0, t; }"
        : "=r"(a) : "l"(p));
    return a;
}

#define CP_ASYNC16(dst, src) \
    asm volatile("cp.async.cg.shared.global [%0], [%1], 16;" :: "r"(dst), "l"(src))
#define CP_COMMIT()  asm volatile("cp.async.commit_group;" ::: "memory")
#define CP_WAIT(n)   asm volatile("cp.async.wait_group %0;" :: "n"(n) : "memory")

#define LDSM4(r, addr) \
    asm volatile("ldmatrix.sync.aligned.m8n8.x4.shared.b16 {%0,%1,%2,%3}, [%4];" \
        : "=r"((r)[0]), "=r"((r)[1]), "=r"((r)[2]), "=r"((r)[3]) : "r"(addr))

#define MMA16816(c, a, bb0, bb1) \
    asm volatile("mma.sync.aligned.m16n8k16.row.col.f32.f16.f16.f32 " \
        "{%0,%1,%2,%3}, {%4,%5,%6,%7}, {%8,%9}, {%0,%1,%2,%3};" \
        : "+f"((c)[0]), "+f"((c)[1]), "+f"((c)[2]), "+f"((c)[3]) \
        : "r"((a)[0]), "r"((a)[1]), "r"((a)[2]), "r"((a)[3]), "r"(bb0), "r"(bb1))

// ---------------- fp32 -> fp16 converters ----------------------------------
__global__ void __launch_bounds__(256)
act_split(const float* __restrict__ src)
{
    size_t i = ((size_t)blockIdx.x * 256 + threadIdx.x) * 8;
    float4 v0 = *(const float4*)(src + i);
    float4 v1 = *(const float4*)(src + i + 4);
    __half2 h0 = __floats2half2_rn(v0.x, v0.y);
    __half2 h1 = __floats2half2_rn(v0.z, v0.w);
    __half2 h2 = __floats2half2_rn(v1.x, v1.y);
    __half2 h3 = __floats2half2_rn(v1.z, v1.w);
    uint4 o;
    o.x = *(uint32_t*)&h0; o.y = *(uint32_t*)&h1;
    o.z = *(uint32_t*)&h2; o.w = *(uint32_t*)&h3;
    *(uint4*)(g_ah + i) = o;
}

// weights: (hi | lo) planes, row stride 768 halves. W: 1 = qkv_w, 2 = proj_w
template<int W>
__global__ void __launch_bounds__(256)
w_split(const float* __restrict__ w, int total4)
{
    int i = blockIdx.x * 256 + threadIdx.x;
    if (i >= total4) return;
    __half* dst = (W == 1) ? g_wq2 : g_wp2;
    int e = i << 2;
    int r = e / DIMC, k = e - r * DIMC;
    float4 v = *(const float4*)(w + e);
    float f[4] = {v.x, v.y, v.z, v.w};
    __half hi[4], lo[4];
    #pragma unroll
    for (int q = 0; q < 4; q++) {
        hi[q] = __float2half_rn(f[q]);
        lo[q] = __float2half_rn(f[q] - __half2float(hi[q]));
    }
    __half2 hh0 = __halves2half2(hi[0], hi[1]);
    __half2 hh1 = __halves2half2(hi[2], hi[3]);
    __half2 ll0 = __halves2half2(lo[0], lo[1]);
    __half2 ll1 = __halves2half2(lo[2], lo[3]);
    size_t ro = (size_t)r * 768 + k;
    *(uint2*)(dst + ro)       = make_uint2(*(uint32_t*)&hh0, *(uint32_t*)&hh1);
    *(uint2*)(dst + ro + 384) = make_uint2(*(uint32_t*)&ll0, *(uint32_t*)&ll1);
}

// ---------------- HMMA GEMM: C[M,N] = Ah[M,384] * W2[N,768]^T --------------
// Keff = 768: chunks 0-5 use W hi planes, 6-11 lo planes; A chunk = c % 6.
// BM=128, BN=128, BK=64 (128B rows, xor swizzle), 3-stage cp.async pipeline,
// 2 CTAs/SM. 8 warps (4 along M x 2 along N), warp tile 32x64, m16n8k16.
#define STAGEB 32768
#define CHUNKS 12
#define SMEM_DYN (3 * STAGEB)

// MODE 0: QKV -> g_qkv with bias + q-scale + [s,b,h,n,d] permute
// MODE 1: proj -> C row-major [M,384] + bias
template<int MODE>
__global__ void __launch_bounds__(256, 2)
mma_gemm(const float* __restrict__ bias, float* __restrict__ C)
{
    extern __shared__ __align__(128) char smem[];
    const uint32_t sbase = smem_u32(smem);
    const int t    = threadIdx.x;
    const int wid  = t >> 5, lane = t & 31;
    const int bn   = blockIdx.x * 128;
    const int bm   = blockIdx.y * 128;

    const char* Ab = (const char*)g_ah + (size_t)bm * 768;
    const char* Bb = (const char*)((MODE == 0) ? g_wq2 : g_wp2) + (size_t)bn * 1536;

    auto load = [&](int c) {
        const int st = c % 3;
        const uint32_t sA = sbase + st * STAGEB;
        const uint32_t sB = sA + 16384;
        const int ao = (c % 6) * 128;
        const int bo = c * 128;
        #pragma unroll
        for (int i = 0; i < 4; i++) {
            int idx = t + i * 256;
            int r = idx >> 3, sg = idx & 7;
            CP_ASYNC16(sA + r * 128 + ((sg ^ (r & 7)) << 4),
                       Ab + (size_t)r * 768 + ao + sg * 16);
        }
        #pragma unroll
        for (int i = 0; i < 4; i++) {
            int idx = t + i * 256;
            int r = idx >> 3, sg = idx & 7;
            CP_ASYNC16(sB + r * 128 + ((sg ^ (r & 7)) << 4),
                       Bb + (size_t)r * 1536 + bo + sg * 16);
        }
    };

    float acc[2][8][4];
    #pragma unroll
    for (int m = 0; m < 2; m++)
        #pragma unroll
        for (int n = 0; n < 8; n++)
            #pragma unroll
            for (int q = 0; q < 4; q++) acc[m][n][q] = 0.f;

    load(0); CP_COMMIT();
    load(1); CP_COMMIT();

    const int wm = wid & 3, wn = wid >> 2;
    const int lrow = lane & 15, lkh = lane >> 4;
    const int lx = lrow & 7;               // row-dependent part of swizzle
    const int ar0 = wm * 32 + lrow, ar1 = ar0 + 16;
    const int br0 = wn * 64 + lrow;

    for (int j = 0; j < CHUNKS; j++) {
        CP_WAIT(1);
        __syncthreads();
        if (j + 2 < CHUNKS) load(j + 2);
        CP_COMMIT();

        const uint32_t sA = sbase + (j % 3) * STAGEB;
        const uint32_t sB = sA + 16384;
        #pragma unroll
        for (int ks = 0; ks < 4; ks++) {
            const int kx = (((ks << 1) | lkh) ^ lx) << 4;
            uint32_t a0[4], a1[4], b0[4], b1[4], b2[4], b3[4];
            LDSM4(a0, sA + ar0 * 128 + kx);
            LDSM4(a1, sA + ar1 * 128 + kx);
            LDSM4(b0, sB + (br0     ) * 128 + kx);
            LDSM4(b1, sB + (br0 + 16) * 128 + kx);
            LDSM4(b2, sB + (br0 + 32) * 128 + kx);
            LDSM4(b3, sB + (br0 + 48) * 128 + kx);
            MMA16816(acc[0][0], a0, b0[0], b0[2]);
            MMA16816(acc[0][1], a0, b0[1], b0[3]);
            MMA16816(acc[0][2], a0, b1[0], b1[2]);
            MMA16816(acc[0][3], a0, b1[1], b1[3]);
            MMA16816(acc[0][4], a0, b2[0], b2[2]);
            MMA16816(acc[0][5], a0, b2[1], b2[3]);
            MMA16816(acc[0][6], a0, b3[0], b3[2]);
            MMA16816(acc[0][7], a0, b3[1], b3[3]);
            MMA16816(acc[1][0], a1, b0[0], b0[2]);
            MMA16816(acc[1][1], a1, b0[1], b0[3]);
            MMA16816(acc[1][2], a1, b1[0], b1[2]);
            MMA16816(acc[1][3], a1, b1[1], b1[3]);
            MMA16816(acc[1][4], a1, b2[0], b2[2]);
            MMA16816(acc[1][5], a1, b2[1], b2[3]);
            MMA16816(acc[1][6], a1, b3[0], b3[2]);
            MMA16816(acc[1][7], a1, b3[1], b3[3]);
        }
    }

    // ---- epilogue: C frag thread map: rows +tq (+8), cols +tr*2 ----
    const int tq = lane >> 2, tr = lane & 3;
    if (MODE == 0) {
        const int s = bn / DIMC;                 // BN=128, 384%128==0 -> const
        const float scl = (s == 0) ? 0.17677669529663687f : 1.0f;
        #pragma unroll
        for (int mt = 0; mt < 2; mt++) {
            const int rb = bm + wm * 32 + mt * 16 + tq;
            #pragma unroll
            for (int pr = 0; pr < 2; pr++) {
                const int gi = rb + pr * 8;
                const int b = gi / NTOK, n = gi - b * NTOK;
                #pragma unroll
                for (int nt = 0; nt < 8; nt++) {
                    const int gj = bn + wn * 64 + nt * 8 + tr * 2;
                    const int h = (gj - s * DIMC) >> 5, d = gj & 31;
                    float2 bb = *(const float2*)(bias + gj);
                    float2 o;
                    o.x = (acc[mt][nt][pr * 2 + 0] + bb.x) * scl;
                    o.y = (acc[mt][nt][pr * 2 + 1] + bb.y) * scl;
                    *(float2*)(g_qkv + (size_t)s * S3 +
                               (((size_t)b * NH + h) * NTOK + n) * HD + d) = o;
                }
            }
        }
    } else {
        #pragma unroll
        for (int mt = 0; mt < 2; mt++) {
            const int rb = bm + wm * 32 + mt * 16 + tq;
            #pragma unroll
            for (int pr = 0; pr < 2; pr++) {
                const int gi = rb + pr * 8;
                #pragma unroll
                for (int nt = 0; nt < 8; nt++) {
                    const int gj = bn + wn * 64 + nt * 8 + tr * 2;
                    float2 bb = *(const float2*)(bias + gj);
                    float2 o;
                    o.x = acc[mt][nt][pr * 2 + 0] + bb.x;
                    o.y = acc[mt][nt][pr * 2 + 1] + bb.y;
                    *(float2*)(C + (size_t)gi * DIMC + gj) = o;
                }
            }
        }
    }
}

// ---------------- fused window attention -----------------------------------
// 224 threads. Output written as fp16 directly into g_ah (proj GEMM's A).
__device__ __forceinline__ ull pk2(float x, float y) {
    ull r; asm("mov.b64 %0,{%1,%2};" : "=l"(r) : "f"(x), "f"(y)); return r;
}
__device__ __forceinline__ void up2(ull v, float& x, float& y) {
    asm("mov.b64 {%0,%1},%2;" : "=f"(x), "=f"(y) : "l"(v));
}
__device__ __forceinline__ ull fma2(ull a, ull b, ull c) {
    ull d; asm("fma.rn.f32x2 %0,%1,%2,%3;" : "=l"(d) : "l"(a), "l"(b), "l"(c)); return d;
}

#define ATTN_T 224

__global__ void __launch_bounds__(ATTN_T)
attn_kernel(const float* __restrict__ mask, const float* __restrict__ rpb,
            const int* __restrict__ relidx)
{
    __shared__ float qT[32][52];
    __shared__ float kT[32][52];
    __shared__ float vS[49][32];
    __shared__ float S[52][52];
    __shared__ float biasS[169];
    __shared__ unsigned char ridxS[2401];

    int bh = blockIdx.x;
    int b  = bh / NH;
    int h  = bh - b * NH;
    int w  = b & (NWIN - 1);
    int t  = threadIdx.x;

    const float* qg = g_qkv + (size_t)bh * (NTOK * HD);
    const float* kg = qg + S3;
    const float* vg = qg + 2 * (size_t)S3;

    for (int i = t; i < NTOK * HD; i += ATTN_T) {
        int n = i >> 5, j = i & 31;
        qT[j][n] = qg[i];
        kT[j][n] = kg[i];
        vS[n][j] = vg[i];
    }
    if (t < 96) {
        int j = t / 3, cp = 49 + (t % 3);
        qT[j][cp] = 0.f; kT[j][cp] = 0.f;
    }
    for (int i = t; i < 169; i += ATTN_T) biasS[i] = rpb[i * NH + h];
    for (int i = t; i < 2401; i += ATTN_T) ridxS[i] = (unsigned char)relidx[i];
    __syncthreads();

    if (t < 169) {
        int n0 = (t / 13) << 2, m0 = (t % 13) << 2;
        ull a2c[4][2];
        #pragma unroll
        for (int i = 0; i < 4; i++) { a2c[i][0] = 0ull; a2c[i][1] = 0ull; }
        #pragma unroll
        for (int j = 0; j < 32; j++) {
            float4 a  = *(const float4*)&qT[j][n0];
            float4 k4 = *(const float4*)&kT[j][m0];
            ull b01 = pk2(k4.x, k4.y), b23 = pk2(k4.z, k4.w);
            ull a0 = pk2(a.x, a.x), a1 = pk2(a.y, a.y);
            ull a2 = pk2(a.z, a.z), a3 = pk2(a.w, a.w);
            a2c[0][0] = fma2(a0, b01, a2c[0][0]); a2c[0][1] = fma2(a0, b23, a2c[0][1]);
            a2c[1][0] = fma2(a1, b01, a2c[1][0]); a2c[1][1] = fma2(a1, b23, a2c[1][1]);
            a2c[2][0] = fma2(a2, b01, a2c[2][0]); a2c[2][1] = fma2(a2, b23, a2c[2][1]);
            a2c[3][0] = fma2(a3, b01, a2c[3][0]); a2c[3][1] = fma2(a3, b23, a2c[3][1]);
        }
        const float* mrow = mask + (size_t)w * (NTOK * NTOK);
        #pragma unroll
        for (int i = 0; i < 4; i++) {
            float cc[4];
            up2(a2c[i][0], cc[0], cc[1]);
            up2(a2c[i][1], cc[2], cc[3]);
            int n = n0 + i;
            #pragma unroll
            for (int j2 = 0; j2 < 4; j2++) {
                int m = m0 + j2;
                float val;
                if (m < NTOK && n < NTOK)
                    val = cc[j2] + biasS[ridxS[n * NTOK + m]] + mrow[n * NTOK + m];
                else
                    val = -1e30f;
                S[n][m] = val;
            }
        }
    }
    __syncthreads();

    // ---- parallel softmax: 4 threads per row, shfl reductions --------------
    {
        int row = t >> 2, p = t & 3;
        bool act = row < NTOK;
        int c0 = p * 13;
        int cn = (p == 3) ? 10 : 13;         // 13+13+13+10 = 49
        float mx = -1e30f;
        if (act)
            for (int c = 0; c < cn; c++) mx = fmaxf(mx, S[row][c0 + c]);
        mx = fmaxf(mx, __shfl_xor_sync(0xffffffffu, mx, 1));
        mx = fmaxf(mx, __shfl_xor_sync(0xffffffffu, mx, 2));
        float sum = 0.f;
        if (act)
            for (int c = 0; c < cn; c++) {
                float e = __expf(S[row][c0 + c] - mx);
                S[row][c0 + c] = e;
                sum += e;
            }
        sum += __shfl_xor_sync(0xffffffffu, sum, 1);
        sum += __shfl_xor_sync(0xffffffffu, sum, 2);
        float inv = 1.0f / sum;
        if (act)
            for (int c = 0; c < cn; c++) S[row][c0 + c] *= inv;
    }
    __syncthreads();

    if (t < 104) {
        int n0 = (t >> 3) << 2, d0 = (t & 7) << 2;
        ull a2c[4][2];
        #pragma unroll
        for (int i = 0; i < 4; i++) { a2c[i][0] = 0ull; a2c[i][1] = 0ull; }
        for (int m = 0; m < NTOK; m++) {
            float4 vv = *(const float4*)&vS[m][d0];
            ull v01 = pk2(vv.x, vv.y), v23 = pk2(vv.z, vv.w);
            #pragma unroll
            for (int i = 0; i < 4; i++) {
                float p = S[n0 + i][m];
                ull pp = pk2(p, p);
                a2c[i][0] = fma2(pp, v01, a2c[i][0]);
                a2c[i][1] = fma2(pp, v23, a2c[i][1]);
            }
        }
        size_t obase = ((size_t)b * NTOK) * DIMC + h * HD + d0;
        #pragma unroll
        for (int i = 0; i < 4; i++) {
            int n = n0 + i;
            if (n < NTOK) {
                float o0, o1, o2, o3;
                up2(a2c[i][0], o0, o1);
                up2(a2c[i][1], o2, o3);
                __half2 p0 = __floats2half2_rn(o0, o1);
                __half2 p1 = __floats2half2_rn(o2, o3);
                *(uint2*)(g_ah + obase + (size_t)n * DIMC) =
                    make_uint2(*(uint32_t*)&p0, *(uint32_t*)&p1);
            }
        }
    }
}

// ---------------- launch ---------------------------------------------------
extern "C" void kernel_launch(void* const* d_in, const int* in_sizes, int n_in,
                              void* d_out, int out_size)
{
    const float* x      = (const float*)d_in[0];
    const float* mask   = (const float*)d_in[1];
    const float* qkv_w  = (const float*)d_in[2];
    const float* qkv_b  = (const float*)d_in[3];
    const float* proj_w = (const float*)d_in[4];
    const float* proj_b = (const float*)d_in[5];
    const float* rpb    = (const float*)d_in[6];
    const int*   relidx = (const int*)d_in[7];
    float* out = (float*)d_out;
    (void)in_sizes; (void)n_in; (void)out_size;

    cudaFuncSetAttribute(mma_gemm<0>, cudaFuncAttributeMaxDynamicSharedMemorySize, SMEM_DYN);
    cudaFuncSetAttribute(mma_gemm<1>, cudaFuncAttributeMaxDynamicSharedMemorySize, SMEM_DYN);

    const int actBlocks = (M_TOTAL * DIMC) / (256 * 8);   // 37632

    // 1) converters
    act_split<<<actBlocks, 256>>>(x);
    w_split<1><<<(1152 * 96 + 255) / 256, 256>>>(qkv_w, 1152 * 96);
    w_split<2><<<(384 * 96 + 255) / 256, 256>>>(proj_w, 384 * 96);

    // 2) QKV projection (HMMA) with fused bias + scale + permute
    mma_gemm<0><<<dim3(1152 / 128, M_TOTAL / 128), 256, SMEM_DYN>>>(qkv_b, nullptr);

    // 3) windowed attention; writes fp16 output straight into g_ah
    attn_kernel<<<BWIN * NH, ATTN_T>>>(mask, rpb, relidx);

    // 4) output projection (HMMA)
    mma_gemm<1><<<dim3(DIMC / 128, M_TOTAL / 128), 256, SMEM_DYN>>>(proj_b, out);
}

// round 13
// speedup vs baseline: 3.4888x; 1.1345x over previous
#include <cuda_runtime.h>
#include <cuda_fp16.h>
#include <cstdint>

#define DIMC   384
#define NH     12
#define HD     32
#define NTOK   49
#define BWIN   4096
#define NWIN   64
#define M_TOTAL (BWIN*NTOK)          // 200704
#define S3      77070336             // 4096*12*49*32  (one of q/k/v)

// ---------------- scratch (__device__ globals; no allocs allowed) -----------
__device__ __align__(16) __half g_qkv[3 * S3];               // q|k|v fp16 [s][b,h,n,d]
__device__ __align__(16) __half g_ah[(size_t)M_TOTAL * 384]; // fp16 activations (x, then attn-out)
__device__ __align__(16) __half g_wq2[1152 * 768];           // qkv_w  (hi|lo)
__device__ __align__(16) __half g_wp2[384 * 768];            // proj_w (hi|lo)

__device__ __forceinline__ uint32_t smem_u32(const void* p) {
    uint32_t a;
    asm("{ .reg .u64 t; cvta.to.shared.u64 t, %1; cvt.u32.u64 %0, t; }"
        : "=r"(a) : "l"(p));
    return a;
}

#define CP_ASYNC16(dst, src) \
    asm volatile("cp.async.cg.shared.global [%0], [%1], 16;" :: "r"(dst), "l"(src))
#define CP_COMMIT()  asm volatile("cp.async.commit_group;" ::: "memory")
#define CP_WAIT(n)   asm volatile("cp.async.wait_group %0;" :: "n"(n) : "memory")

#define LDSM4(r, addr) \
    asm volatile("ldmatrix.sync.aligned.m8n8.x4.shared.b16 {%0,%1,%2,%3}, [%4];" \
        : "=r"((r)[0]), "=r"((r)[1]), "=r"((r)[2]), "=r"((r)[3]) : "r"(addr))

#define MMA16816(c, a, bb0, bb1) \
    asm volatile("mma.sync.aligned.m16n8k16.row.col.f32.f16.f16.f32 " \
        "{%0,%1,%2,%3}, {%4,%5,%6,%7}, {%8,%9}, {%0,%1,%2,%3};" \
        : "+f"((c)[0]), "+f"((c)[1]), "+f"((c)[2]), "+f"((c)[3]) \
        : "r"((a)[0]), "r"((a)[1]), "r"((a)[2]), "r"((a)[3]), "r"(bb0), "r"(bb1))

// ---------------- fp32 -> fp16 converters ----------------------------------
__global__ void __launch_bounds__(256)
act_split(const float* __restrict__ src)
{
    size_t i = ((size_t)blockIdx.x * 256 + threadIdx.x) * 8;
    float4 v0 = *(const float4*)(src + i);
    float4 v1 = *(const float4*)(src + i + 4);
    __half2 h0 = __floats2half2_rn(v0.x, v0.y);
    __half2 h1 = __floats2half2_rn(v0.z, v0.w);
    __half2 h2 = __floats2half2_rn(v1.x, v1.y);
    __half2 h3 = __floats2half2_rn(v1.z, v1.w);
    uint4 o;
    o.x = *(uint32_t*)&h0; o.y = *(uint32_t*)&h1;
    o.z = *(uint32_t*)&h2; o.w = *(uint32_t*)&h3;
    *(uint4*)(g_ah + i) = o;
}

// weights: (hi | lo) planes, row stride 768 halves. W: 1 = qkv_w, 2 = proj_w
template<int W>
__global__ void __launch_bounds__(256)
w_split(const float* __restrict__ w, int total4)
{
    int i = blockIdx.x * 256 + threadIdx.x;
    if (i >= total4) return;
    __half* dst = (W == 1) ? g_wq2 : g_wp2;
    int e = i << 2;
    int r = e / DIMC, k = e - r * DIMC;
    float4 v = *(const float4*)(w + e);
    float f[4] = {v.x, v.y, v.z, v.w};
    __half hi[4], lo[4];
    #pragma unroll
    for (int q = 0; q < 4; q++) {
        hi[q] = __float2half_rn(f[q]);
        lo[q] = __float2half_rn(f[q] - __half2float(hi[q]));
    }
    __half2 hh0 = __halves2half2(hi[0], hi[1]);
    __half2 hh1 = __halves2half2(hi[2], hi[3]);
    __half2 ll0 = __halves2half2(lo[0], lo[1]);
    __half2 ll1 = __halves2half2(lo[2], lo[3]);
    size_t ro = (size_t)r * 768 + k;
    *(uint2*)(dst + ro)       = make_uint2(*(uint32_t*)&hh0, *(uint32_t*)&hh1);
    *(uint2*)(dst + ro + 384) = make_uint2(*(uint32_t*)&ll0, *(uint32_t*)&ll1);
}

// ---------------- HMMA GEMM: C[M,N] = Ah[M,384] * W2[N,768]^T --------------
// Keff = 768: chunks 0-5 use W hi planes, 6-11 lo planes; A chunk = c % 6.
// BM=128, BN=128, BK=64 (128B rows, xor swizzle), 3-stage cp.async pipeline,
// 2 CTAs/SM. 8 warps (4 along M x 2 along N), warp tile 32x64, m16n8k16.
#define STAGEB 32768
#define CHUNKS 12
#define SMEM_DYN (3 * STAGEB)

// MODE 0: QKV -> g_qkv (fp16) with bias + q-scale + [s,b,h,n,d] permute
// MODE 1: proj -> C row-major [M,384] + bias (fp32)
template<int MODE>
__global__ void __launch_bounds__(256, 2)
mma_gemm(const float* __restrict__ bias, float* __restrict__ C)
{
    extern __shared__ __align__(128) char smem[];
    const uint32_t sbase = smem_u32(smem);
    const int t    = threadIdx.x;
    const int wid  = t >> 5, lane = t & 31;
    const int bn   = blockIdx.x * 128;
    const int bm   = blockIdx.y * 128;

    const char* Ab = (const char*)g_ah + (size_t)bm * 768;
    const char* Bb = (const char*)((MODE == 0) ? g_wq2 : g_wp2) + (size_t)bn * 1536;

    auto load = [&](int c) {
        const int st = c % 3;
        const uint32_t sA = sbase + st * STAGEB;
        const uint32_t sB = sA + 16384;
        const int ao = (c % 6) * 128;
        const int bo = c * 128;
        #pragma unroll
        for (int i = 0; i < 4; i++) {
            int idx = t + i * 256;
            int r = idx >> 3, sg = idx & 7;
            CP_ASYNC16(sA + r * 128 + ((sg ^ (r & 7)) << 4),
                       Ab + (size_t)r * 768 + ao + sg * 16);
        }
        #pragma unroll
        for (int i = 0; i < 4; i++) {
            int idx = t + i * 256;
            int r = idx >> 3, sg = idx & 7;
            CP_ASYNC16(sB + r * 128 + ((sg ^ (r & 7)) << 4),
                       Bb + (size_t)r * 1536 + bo + sg * 16);
        }
    };

    float acc[2][8][4];
    #pragma unroll
    for (int m = 0; m < 2; m++)
        #pragma unroll
        for (int n = 0; n < 8; n++)
            #pragma unroll
            for (int q = 0; q < 4; q++) acc[m][n][q] = 0.f;

    load(0); CP_COMMIT();
    load(1); CP_COMMIT();

    const int wm = wid & 3, wn = wid >> 2;
    const int lrow = lane & 15, lkh = lane >> 4;
    const int lx = lrow & 7;               // row-dependent part of swizzle
    const int ar0 = wm * 32 + lrow, ar1 = ar0 + 16;
    const int br0 = wn * 64 + lrow;

    for (int j = 0; j < CHUNKS; j++) {
        CP_WAIT(1);
        __syncthreads();
        if (j + 2 < CHUNKS) load(j + 2);
        CP_COMMIT();

        const uint32_t sA = sbase + (j % 3) * STAGEB;
        const uint32_t sB = sA + 16384;
        #pragma unroll
        for (int ks = 0; ks < 4; ks++) {
            const int kx = (((ks << 1) | lkh) ^ lx) << 4;
            uint32_t a0[4], a1[4], b0[4], b1[4], b2[4], b3[4];
            LDSM4(a0, sA + ar0 * 128 + kx);
            LDSM4(a1, sA + ar1 * 128 + kx);
            LDSM4(b0, sB + (br0     ) * 128 + kx);
            LDSM4(b1, sB + (br0 + 16) * 128 + kx);
            LDSM4(b2, sB + (br0 + 32) * 128 + kx);
            LDSM4(b3, sB + (br0 + 48) * 128 + kx);
            MMA16816(acc[0][0], a0, b0[0], b0[2]);
            MMA16816(acc[0][1], a0, b0[1], b0[3]);
            MMA16816(acc[0][2], a0, b1[0], b1[2]);
            MMA16816(acc[0][3], a0, b1[1], b1[3]);
            MMA16816(acc[0][4], a0, b2[0], b2[2]);
            MMA16816(acc[0][5], a0, b2[1], b2[3]);
            MMA16816(acc[0][6], a0, b3[0], b3[2]);
            MMA16816(acc[0][7], a0, b3[1], b3[3]);
            MMA16816(acc[1][0], a1, b0[0], b0[2]);
            MMA16816(acc[1][1], a1, b0[1], b0[3]);
            MMA16816(acc[1][2], a1, b1[0], b1[2]);
            MMA16816(acc[1][3], a1, b1[1], b1[3]);
            MMA16816(acc[1][4], a1, b2[0], b2[2]);
            MMA16816(acc[1][5], a1, b2[1], b2[3]);
            MMA16816(acc[1][6], a1, b3[0], b3[2]);
            MMA16816(acc[1][7], a1, b3[1], b3[3]);
        }
    }

    // ---- epilogue: C frag thread map: rows +tq (+8), cols +tr*2 ----
    const int tq = lane >> 2, tr = lane & 3;
    if (MODE == 0) {
        const int s = bn / DIMC;                 // BN=128, 384%128==0 -> const
        const float scl = (s == 0) ? 0.17677669529663687f : 1.0f;
        #pragma unroll
        for (int mt = 0; mt < 2; mt++) {
            const int rb = bm + wm * 32 + mt * 16 + tq;
            #pragma unroll
            for (int pr = 0; pr < 2; pr++) {
                const int gi = rb + pr * 8;
                const int b = gi / NTOK, n = gi - b * NTOK;
                #pragma unroll
                for (int nt = 0; nt < 8; nt++) {
                    const int gj = bn + wn * 64 + nt * 8 + tr * 2;
                    const int h = (gj - s * DIMC) >> 5, d = gj & 31;
                    float2 bb = *(const float2*)(bias + gj);
                    __half2 hv = __floats2half2_rn(
                        (acc[mt][nt][pr * 2 + 0] + bb.x) * scl,
                        (acc[mt][nt][pr * 2 + 1] + bb.y) * scl);
                    *(uint32_t*)(g_qkv + (size_t)s * S3 +
                                 (((size_t)b * NH + h) * NTOK + n) * HD + d)
                        = *(uint32_t*)&hv;
                }
            }
        }
    } else {
        #pragma unroll
        for (int mt = 0; mt < 2; mt++) {
            const int rb = bm + wm * 32 + mt * 16 + tq;
            #pragma unroll
            for (int pr = 0; pr < 2; pr++) {
                const int gi = rb + pr * 8;
                #pragma unroll
                for (int nt = 0; nt < 8; nt++) {
                    const int gj = bn + wn * 64 + nt * 8 + tr * 2;
                    float2 bb = *(const float2*)(bias + gj);
                    float2 o;
                    o.x = acc[mt][nt][pr * 2 + 0] + bb.x;
                    o.y = acc[mt][nt][pr * 2 + 1] + bb.y;
                    *(float2*)(C + (size_t)gi * DIMC + gj) = o;
                }
            }
        }
    }
}

// ---------------- fused window attention, HMMA -----------------------------
// One block per (window, head). 256 threads = 8 warps.
// QK^T 64x64x32, softmax (+bias+mask) fp32, PV 64x32x64, fp16 out to g_ah.
#define ATT_T 256

__global__ void __launch_bounds__(ATT_T)
attn_kernel(const float* __restrict__ mask, const float* __restrict__ rpb,
            const int* __restrict__ relidx)
{
    __shared__ __align__(16) __half qS[64 * 40];   // rows n, 32 halves + 8 pad (80B stride)
    __shared__ __align__(16) __half kS[64 * 40];   // rows m
    __shared__ __align__(16) __half vT[32 * 72];   // rows d, 64 halves + 8 pad (144B stride)
    __shared__ __align__(16) float  Ssm[64 * 68];  // scores fp32
    __shared__ __align__(16) __half P[64 * 72];    // probs fp16 (144B stride)
    __shared__ float biasS[169];
    __shared__ unsigned char ridxS[2401];

    const int bh = blockIdx.x;
    const int b  = bh / NH;
    const int h  = bh - b * NH;
    const int w  = b & (NWIN - 1);
    const int t  = threadIdx.x;
    const int wid = t >> 5, lane = t & 31;
    const int lrow = lane & 15, lkh = lane >> 4;

    const __half* qg = g_qkv + (size_t)bh * (NTOK * HD);
    const __half* kg = qg + S3;
    const __half* vg = qg + 2 * (size_t)S3;

    // ---- stage q,k (row-major, pad) + v transposed ----
    for (int i = t; i < 784; i += ATT_T) {           // 49*32/2 uint32s
        int n = i >> 4, dp = (i & 15) << 1;
        *(uint32_t*)(qS + n * 40 + dp) = ((const uint32_t*)qg)[i];
        *(uint32_t*)(kS + n * 40 + dp) = ((const uint32_t*)kg)[i];
    }
    for (int i = t; i < 240; i += ATT_T) {           // zero pad rows 49..63
        int r = 49 + (i / 16), dp = (i & 15) << 1;
        *(uint32_t*)(qS + r * 40 + dp) = 0u;
        *(uint32_t*)(kS + r * 40 + dp) = 0u;
    }
    for (int i = t; i < 1568; i += ATT_T) {          // v transpose [m][d]->[d][m]
        int m = i >> 5, d = i & 31;
        vT[d * 72 + m] = vg[i];
    }
    for (int i = t; i < 480; i += ATT_T) {           // zero vT cols m=49..63
        int d = i / 15, m = 49 + (i % 15);
        vT[d * 72 + m] = __float2half(0.f);
    }
    for (int i = t; i < 169; i += ATT_T) biasS[i] = rpb[i * NH + h];
    for (int i = t; i < 2401; i += ATT_T) ridxS[i] = (unsigned char)relidx[i];
    __syncthreads();

    // ---- S = q k^T (64x64x32): 8 warps = 4(n) x 2(m-halves) ----
    {
        const uint32_t qb = smem_u32(qS), kb = smem_u32(kS);
        const int wm = wid & 3, wn = wid >> 2;
        float acc[4][4];
        #pragma unroll
        for (int i = 0; i < 4; i++)
            #pragma unroll
            for (int q = 0; q < 4; q++) acc[i][q] = 0.f;
        #pragma unroll
        for (int ks = 0; ks < 2; ks++) {
            const uint32_t off = (uint32_t)(((ks << 1) | lkh) << 4);
            uint32_t a[4], b0[4], b1[4];
            LDSM4(a,  qb + (wm * 16 + lrow) * 80 + off);
            LDSM4(b0, kb + (wn * 32 + lrow) * 80 + off);
            LDSM4(b1, kb + (wn * 32 + 16 + lrow) * 80 + off);
            MMA16816(acc[0], a, b0[0], b0[2]);
            MMA16816(acc[1], a, b0[1], b0[3]);
            MMA16816(acc[2], a, b1[0], b1[2]);
            MMA16816(acc[3], a, b1[1], b1[3]);
        }
        const int tq = lane >> 2, tr = lane & 3;
        #pragma unroll
        for (int nt = 0; nt < 4; nt++)
            #pragma unroll
            for (int q = 0; q < 4; q++) {
                int row = wm * 16 + tq + (q >> 1) * 8;
                int col = wn * 32 + nt * 8 + tr * 2 + (q & 1);
                Ssm[row * 68 + col] = acc[nt][q];
            }
    }
    __syncthreads();

    // ---- bias + mask + softmax: 4 threads/row, shfl reductions ----
    {
        int row = t >> 2, p = t & 3;
        bool act = row < NTOK;
        int c0 = p * 13;
        int cn = (p == 3) ? 10 : 13;                 // 13+13+13+10 = 49
        const float* mrow = mask + (size_t)w * (NTOK * NTOK) + row * NTOK;
        float mx = -1e30f;
        if (act)
            for (int c = 0; c < cn; c++) {
                int m = c0 + c;
                float v = Ssm[row * 68 + m] + biasS[ridxS[row * NTOK + m]] + mrow[m];
                Ssm[row * 68 + m] = v;
                mx = fmaxf(mx, v);
            }
        mx = fmaxf(mx, __shfl_xor_sync(0xffffffffu, mx, 1));
        mx = fmaxf(mx, __shfl_xor_sync(0xffffffffu, mx, 2));
        float sum = 0.f;
        if (act)
            for (int c = 0; c < cn; c++) {
                float e = __expf(Ssm[row * 68 + c0 + c] - mx);
                Ssm[row * 68 + c0 + c] = e;
                sum += e;
            }
        sum += __shfl_xor_sync(0xffffffffu, sum, 1);
        sum += __shfl_xor_sync(0xffffffffu, sum, 2);
        float inv = 1.0f / sum;
        if (act)
            for (int c = 0; c < cn; c++) Ssm[row * 68 + c0 + c] *= inv;
    }
    __syncthreads();

    // ---- pack P to fp16 (zero outside 49x49) ----
    for (int i = t; i < 2048; i += ATT_T) {
        int n = i >> 5, mp = (i & 31) << 1;
        float v0 = 0.f, v1 = 0.f;
        if (n < NTOK) {
            if (mp < NTOK)     v0 = Ssm[n * 68 + mp];
            if (mp + 1 < NTOK) v1 = Ssm[n * 68 + mp + 1];
        }
        __half2 hp = __floats2half2_rn(v0, v1);
        *(uint32_t*)(P + n * 72 + mp) = *(uint32_t*)&hp;
    }
    __syncthreads();

    // ---- out = P V (64x32x64): 8 warps = 4(n) x 2(d-halves) ----
    {
        const uint32_t pb = smem_u32(P), vb = smem_u32(vT);
        const int wpn = wid & 3, wd = wid >> 2;
        float acc[2][4];
        #pragma unroll
        for (int i = 0; i < 2; i++)
            #pragma unroll
            for (int q = 0; q < 4; q++) acc[i][q] = 0.f;
        #pragma unroll
        for (int ks = 0; ks < 4; ks++) {
            const uint32_t off = (uint32_t)(((ks << 1) | lkh) << 4);
            uint32_t a[4], bb[4];
            LDSM4(a,  pb + (wpn * 16 + lrow) * 144 + off);
            LDSM4(bb, vb + (wd * 16 + lrow) * 144 + off);
            MMA16816(acc[0], a, bb[0], bb[2]);
            MMA16816(acc[1], a, bb[1], bb[3]);
        }
        const int tq = lane >> 2, tr = lane & 3;
        #pragma unroll
        for (int dt = 0; dt < 2; dt++)
            #pragma unroll
            for (int pr = 0; pr < 2; pr++) {
                int n = wpn * 16 + tq + pr * 8;
                if (n < NTOK) {
                    int d = wd * 16 + dt * 8 + tr * 2;
                    __half2 hv = __floats2half2_rn(acc[dt][pr * 2 + 0],
                                                   acc[dt][pr * 2 + 1]);
                    *(uint32_t*)(g_ah + ((size_t)b * NTOK + n) * DIMC + h * HD + d)
                        = *(uint32_t*)&hv;
                }
            }
    }
}

// ---------------- launch ---------------------------------------------------
extern "C" void kernel_launch(void* const* d_in, const int* in_sizes, int n_in,
                              void* d_out, int out_size)
{
    const float* x      = (const float*)d_in[0];
    const float* mask   = (const float*)d_in[1];
    const float* qkv_w  = (const float*)d_in[2];
    const float* qkv_b  = (const float*)d_in[3];
    const float* proj_w = (const float*)d_in[4];
    const float* proj_b = (const float*)d_in[5];
    const float* rpb    = (const float*)d_in[6];
    const int*   relidx = (const int*)d_in[7];
    float* out = (float*)d_out;
    (void)in_sizes; (void)n_in; (void)out_size;

    cudaFuncSetAttribute(mma_gemm<0>, cudaFuncAttributeMaxDynamicSharedMemorySize, SMEM_DYN);
    cudaFuncSetAttribute(mma_gemm<1>, cudaFuncAttributeMaxDynamicSharedMemorySize, SMEM_DYN);

    const int actBlocks = (M_TOTAL * DIMC) / (256 * 8);   // 37632

    // 1) converters
    act_split<<<actBlocks, 256>>>(x);
    w_split<1><<<(1152 * 96 + 255) / 256, 256>>>(qkv_w, 1152 * 96);
    w_split<2><<<(384 * 96 + 255) / 256, 256>>>(proj_w, 384 * 96);

    // 2) QKV projection (HMMA), fp16 q/k/v out, fused bias + scale + permute
    mma_gemm<0><<<dim3(1152 / 128, M_TOTAL / 128), 256, SMEM_DYN>>>(qkv_b, nullptr);

    // 3) windowed attention (HMMA QK^T + softmax + HMMA PV), fp16 out -> g_ah
    attn_kernel<<<BWIN * NH, ATT_T>>>(mask, rpb, relidx);

    // 4) output projection (HMMA)
    mma_gemm<1><<<dim3(DIMC / 128, M_TOTAL / 128), 256, SMEM_DYN>>>(proj_b, out);
}

// round 14
// speedup vs baseline: 4.1424x; 1.1874x over previous
#include <cuda_runtime.h>
#include <cuda_fp16.h>
#include <cstdint>

#define DIMC   384
#define NH     12
#define HD     32
#define NTOK   49
#define BWIN   4096
#define NWIN   64
#define M_TOTAL (BWIN*NTOK)          // 200704
#define S3      77070336             // 4096*12*49*32  (one of q/k/v)

// ---------------- scratch (__device__ globals; no allocs allowed) -----------
__device__ __align__(16) __half g_qkv[3 * S3];               // q|k|v fp16 [s][b,h,n,d]
__device__ __align__(16) __half g_ah[(size_t)M_TOTAL * 384]; // fp16 activations (x, then attn-out)
__device__ __align__(16) __half g_wq2[1152 * 768];           // qkv_w  (hi|lo)
__device__ __align__(16) __half g_wp2[384 * 768];            // proj_w (hi|lo)
__device__ __align__(16) float  g_bm[NWIN * NH * NTOK * 52]; // bias+mask table

__device__ __forceinline__ uint32_t smem_u32(const void* p) {
    uint32_t a;
    asm("{ .reg .u64 t; cvta.to.shared.u64 t, %1; cvt.u32.u64 %0, t; }"
        : "=r"(a) : "l"(p));
    return a;
}

#define CP_ASYNC16(dst, src) \
    asm volatile("cp.async.cg.shared.global [%0], [%1], 16;" :: "r"(dst), "l"(src))
#define CP_COMMIT()  asm volatile("cp.async.commit_group;" ::: "memory")
#define CP_WAIT(n)   asm volatile("cp.async.wait_group %0;" :: "n"(n) : "memory")

#define LDSM4(r, addr) \
    asm volatile("ldmatrix.sync.aligned.m8n8.x4.shared.b16 {%0,%1,%2,%3}, [%4];" \
        : "=r"((r)[0]), "=r"((r)[1]), "=r"((r)[2]), "=r"((r)[3]) : "r"(addr))

#define LDSM4T(r, addr) \
    asm volatile("ldmatrix.sync.aligned.m8n8.x4.trans.shared.b16 {%0,%1,%2,%3}, [%4];" \
        : "=r"((r)[0]), "=r"((r)[1]), "=r"((r)[2]), "=r"((r)[3]) : "r"(addr))

#define MMA16816(c, a, bb0, bb1) \
    asm volatile("mma.sync.aligned.m16n8k16.row.col.f32.f16.f16.f32 " \
        "{%0,%1,%2,%3}, {%4,%5,%6,%7}, {%8,%9}, {%0,%1,%2,%3};" \
        : "+f"((c)[0]), "+f"((c)[1]), "+f"((c)[2]), "+f"((c)[3]) \
        : "r"((a)[0]), "r"((a)[1]), "r"((a)[2]), "r"((a)[3]), "r"(bb0), "r"(bb1))

// ---------------- fp32 -> fp16 converters ----------------------------------
__global__ void __launch_bounds__(256)
act_split(const float* __restrict__ src)
{
    size_t i = ((size_t)blockIdx.x * 256 + threadIdx.x) * 8;
    float4 v0 = *(const float4*)(src + i);
    float4 v1 = *(const float4*)(src + i + 4);
    __half2 h0 = __floats2half2_rn(v0.x, v0.y);
    __half2 h1 = __floats2half2_rn(v0.z, v0.w);
    __half2 h2 = __floats2half2_rn(v1.x, v1.y);
    __half2 h3 = __floats2half2_rn(v1.z, v1.w);
    uint4 o;
    o.x = *(uint32_t*)&h0; o.y = *(uint32_t*)&h1;
    o.z = *(uint32_t*)&h2; o.w = *(uint32_t*)&h3;
    *(uint4*)(g_ah + i) = o;
}

// weights: (hi | lo) planes, row stride 768 halves. W: 1 = qkv_w, 2 = proj_w
template<int W>
__global__ void __launch_bounds__(256)
w_split(const float* __restrict__ w, int total4)
{
    int i = blockIdx.x * 256 + threadIdx.x;
    if (i >= total4) return;
    __half* dst = (W == 1) ? g_wq2 : g_wp2;
    int e = i << 2;
    int r = e / DIMC, k = e - r * DIMC;
    float4 v = *(const float4*)(w + e);
    float f[4] = {v.x, v.y, v.z, v.w};
    __half hi[4], lo[4];
    #pragma unroll
    for (int q = 0; q < 4; q++) {
        hi[q] = __float2half_rn(f[q]);
        lo[q] = __float2half_rn(f[q] - __half2float(hi[q]));
    }
    __half2 hh0 = __halves2half2(hi[0], hi[1]);
    __half2 hh1 = __halves2half2(hi[2], hi[3]);
    __half2 ll0 = __halves2half2(lo[0], lo[1]);
    __half2 ll1 = __halves2half2(lo[2], lo[3]);
    size_t ro = (size_t)r * 768 + k;
    *(uint2*)(dst + ro)       = make_uint2(*(uint32_t*)&hh0, *(uint32_t*)&hh1);
    *(uint2*)(dst + ro + 384) = make_uint2(*(uint32_t*)&ll0, *(uint32_t*)&ll1);
}

// ---------------- bias+mask table: g_bm[w][h][n][52] -----------------------
__global__ void __launch_bounds__(256)
bm_build(const float* __restrict__ mask, const float* __restrict__ rpb,
         const int* __restrict__ relidx)
{
    int i = blockIdx.x * 256 + threadIdx.x;      // over 64*12*49*52
    if (i >= NWIN * NH * NTOK * 52) return;
    int m  = i % 52;
    int r  = i / 52;                             // (w*12+h)*49 + n
    int n  = r % NTOK;
    int wh = r / NTOK;
    int h  = wh % NH;
    int w  = wh / NH;
    float v = 0.f;
    if (m < NTOK) {
        int nm = n * NTOK + m;
        v = rpb[relidx[nm] * NH + h] + mask[w * (NTOK * NTOK) + nm];
    }
    g_bm[i] = v;
}

// ---------------- HMMA GEMM: C[M,N] = Ah[M,384] * W2[N,768]^T --------------
// Keff = 768: chunks 0-5 use W hi planes, 6-11 lo planes; A chunk = c % 6.
// BM=128, BN=128, BK=64 (128B rows, xor swizzle), 3-stage cp.async pipeline,
// 2 CTAs/SM. 8 warps (4 along M x 2 along N), warp tile 32x64, m16n8k16.
#define STAGEB 32768
#define CHUNKS 12
#define SMEM_DYN (3 * STAGEB)

// MODE 0: QKV -> g_qkv (fp16) with bias + q-scale + [s,b,h,n,d] permute
// MODE 1: proj -> C row-major [M,384] + bias (fp32)
template<int MODE>
__global__ void __launch_bounds__(256, 2)
mma_gemm(const float* __restrict__ bias, float* __restrict__ C)
{
    extern __shared__ __align__(128) char smem[];
    const uint32_t sbase = smem_u32(smem);
    const int t    = threadIdx.x;
    const int wid  = t >> 5, lane = t & 31;
    const int bn   = blockIdx.x * 128;
    const int bm   = blockIdx.y * 128;

    const char* Ab = (const char*)g_ah + (size_t)bm * 768;
    const char* Bb = (const char*)((MODE == 0) ? g_wq2 : g_wp2) + (size_t)bn * 1536;

    auto load = [&](int c) {
        const int st = c % 3;
        const uint32_t sA = sbase + st * STAGEB;
        const uint32_t sB = sA + 16384;
        const int ao = (c % 6) * 128;
        const int bo = c * 128;
        #pragma unroll
        for (int i = 0; i < 4; i++) {
            int idx = t + i * 256;
            int r = idx >> 3, sg = idx & 7;
            CP_ASYNC16(sA + r * 128 + ((sg ^ (r & 7)) << 4),
                       Ab + (size_t)r * 768 + ao + sg * 16);
        }
        #pragma unroll
        for (int i = 0; i < 4; i++) {
            int idx = t + i * 256;
            int r = idx >> 3, sg = idx & 7;
            CP_ASYNC16(sB + r * 128 + ((sg ^ (r & 7)) << 4),
                       Bb + (size_t)r * 1536 + bo + sg * 16);
        }
    };

    float acc[2][8][4];
    #pragma unroll
    for (int m = 0; m < 2; m++)
        #pragma unroll
        for (int n = 0; n < 8; n++)
            #pragma unroll
            for (int q = 0; q < 4; q++) acc[m][n][q] = 0.f;

    load(0); CP_COMMIT();
    load(1); CP_COMMIT();

    const int wm = wid & 3, wn = wid >> 2;
    const int lrow = lane & 15, lkh = lane >> 4;
    const int lx = lrow & 7;               // row-dependent part of swizzle
    const int ar0 = wm * 32 + lrow, ar1 = ar0 + 16;
    const int br0 = wn * 64 + lrow;

    for (int j = 0; j < CHUNKS; j++) {
        CP_WAIT(1);
        __syncthreads();
        if (j + 2 < CHUNKS) load(j + 2);
        CP_COMMIT();

        const uint32_t sA = sbase + (j % 3) * STAGEB;
        const uint32_t sB = sA + 16384;
        #pragma unroll
        for (int ks = 0; ks < 4; ks++) {
            const int kx = (((ks << 1) | lkh) ^ lx) << 4;
            uint32_t a0[4], a1[4], b0[4], b1[4], b2[4], b3[4];
            LDSM4(a0, sA + ar0 * 128 + kx);
            LDSM4(a1, sA + ar1 * 128 + kx);
            LDSM4(b0, sB + (br0     ) * 128 + kx);
            LDSM4(b1, sB + (br0 + 16) * 128 + kx);
            LDSM4(b2, sB + (br0 + 32) * 128 + kx);
            LDSM4(b3, sB + (br0 + 48) * 128 + kx);
            MMA16816(acc[0][0], a0, b0[0], b0[2]);
            MMA16816(acc[0][1], a0, b0[1], b0[3]);
            MMA16816(acc[0][2], a0, b1[0], b1[2]);
            MMA16816(acc[0][3], a0, b1[1], b1[3]);
            MMA16816(acc[0][4], a0, b2[0], b2[2]);
            MMA16816(acc[0][5], a0, b2[1], b2[3]);
            MMA16816(acc[0][6], a0, b3[0], b3[2]);
            MMA16816(acc[0][7], a0, b3[1], b3[3]);
            MMA16816(acc[1][0], a1, b0[0], b0[2]);
            MMA16816(acc[1][1], a1, b0[1], b0[3]);
            MMA16816(acc[1][2], a1, b1[0], b1[2]);
            MMA16816(acc[1][3], a1, b1[1], b1[3]);
            MMA16816(acc[1][4], a1, b2[0], b2[2]);
            MMA16816(acc[1][5], a1, b2[1], b2[3]);
            MMA16816(acc[1][6], a1, b3[0], b3[2]);
            MMA16816(acc[1][7], a1, b3[1], b3[3]);
        }
    }

    // ---- epilogue: C frag thread map: rows +tq (+8), cols +tr*2 ----
    const int tq = lane >> 2, tr = lane & 3;
    if (MODE == 0) {
        const int s = bn / DIMC;                 // BN=128, 384%128==0 -> const
        const float scl = (s == 0) ? 0.17677669529663687f : 1.0f;
        #pragma unroll
        for (int mt = 0; mt < 2; mt++) {
            const int rb = bm + wm * 32 + mt * 16 + tq;
            #pragma unroll
            for (int pr = 0; pr < 2; pr++) {
                const int gi = rb + pr * 8;
                const int b = gi / NTOK, n = gi - b * NTOK;
                #pragma unroll
                for (int nt = 0; nt < 8; nt++) {
                    const int gj = bn + wn * 64 + nt * 8 + tr * 2;
                    const int h = (gj - s * DIMC) >> 5, d = gj & 31;
                    float2 bb = *(const float2*)(bias + gj);
                    __half2 hv = __floats2half2_rn(
                        (acc[mt][nt][pr * 2 + 0] + bb.x) * scl,
                        (acc[mt][nt][pr * 2 + 1] + bb.y) * scl);
                    *(uint32_t*)(g_qkv + (size_t)s * S3 +
                                 (((size_t)b * NH + h) * NTOK + n) * HD + d)
                        = *(uint32_t*)&hv;
                }
            }
        }
    } else {
        #pragma unroll
        for (int mt = 0; mt < 2; mt++) {
            const int rb = bm + wm * 32 + mt * 16 + tq;
            #pragma unroll
            for (int pr = 0; pr < 2; pr++) {
                const int gi = rb + pr * 8;
                #pragma unroll
                for (int nt = 0; nt < 8; nt++) {
                    const int gj = bn + wn * 64 + nt * 8 + tr * 2;
                    float2 bb = *(const float2*)(bias + gj);
                    float2 o;
                    o.x = acc[mt][nt][pr * 2 + 0] + bb.x;
                    o.y = acc[mt][nt][pr * 2 + 1] + bb.y;
                    *(float2*)(C + (size_t)gi * DIMC + gj) = o;
                }
            }
        }
    }
}

// ---------------- fused window attention, HMMA -----------------------------
// One block per (window, head). 256 threads = 8 warps.
// bm table cp.async'd during QK^T; V consumed via ldmatrix.trans (no
// explicit transpose); normalization folded into the P fp16 pack.
#define ATT_T 256
// smem offsets (bytes) in one static buffer
#define OFF_Q   0            // 64 rows * 80B
#define OFF_K   5120
#define OFF_V   10240
#define OFF_BM  15360        // 49*52 fp32 = 10192
#define OFF_S   25552        // 64*68 fp32 = 17408
#define OFF_INV 42960        // 64 fp32
#define OFF_P   0            // 64 rows * 144B = 9216 (overlays q/k after QK^T)
#define SB_SZ   43264

__global__ void __launch_bounds__(ATT_T)
attn_kernel()
{
    __shared__ __align__(16) char sb[SB_SZ];
    const uint32_t sbu = smem_u32(sb);

    const int bh = blockIdx.x;
    const int b  = bh / NH;
    const int h  = bh - b * NH;
    const int w  = b & (NWIN - 1);
    const int t  = threadIdx.x;
    const int wid = t >> 5, lane = t & 31;
    const int lrow = lane & 15, lkh = lane >> 4;

    const __half* qg = g_qkv + (size_t)bh * (NTOK * HD);
    const __half* kg = qg + S3;
    const __half* vg = qg + 2 * (size_t)S3;

    // ---- bm tile via cp.async (lands during QK^T) ----
    {
        const char* bmg = (const char*)(g_bm + (size_t)(w * NH + h) * (NTOK * 52));
        for (int i = t; i < 637; i += ATT_T)      // 49*52 floats = 637 x 16B
            CP_ASYNC16(sbu + OFF_BM + i * 16, bmg + (size_t)i * 16);
        CP_COMMIT();
    }

    // ---- stage q,k,v rows (80B stride) + zero pad rows 49..63 ----
    for (int i = t; i < 784; i += ATT_T) {        // 49*32/2 uint32s
        int n = i >> 4, dp = (i & 15) << 1;
        *(uint32_t*)(sb + OFF_Q + n * 80 + dp * 2) = ((const uint32_t*)qg)[i];
        *(uint32_t*)(sb + OFF_K + n * 80 + dp * 2) = ((const uint32_t*)kg)[i];
        *(uint32_t*)(sb + OFF_V + n * 80 + dp * 2) = ((const uint32_t*)vg)[i];
    }
    for (int i = t; i < 720; i += ATT_T) {        // 3 arrays * 15 rows * 16 u32
        int arr = i / 240, j = i % 240;
        int r = 49 + (j >> 4), dp = (j & 15) << 1;
        *(uint32_t*)(sb + arr * 5120 + r * 80 + dp * 2) = 0u;
    }
    __syncthreads();

    // ---- S = q k^T (64x64x32): 8 warps = 4(n) x 2(m-halves) ----
    {
        const uint32_t qb = sbu + OFF_Q, kb = sbu + OFF_K;
        const int wm = wid & 3, wn = wid >> 2;
        float acc[4][4];
        #pragma unroll
        for (int i = 0; i < 4; i++)
            #pragma unroll
            for (int q = 0; q < 4; q++) acc[i][q] = 0.f;
        #pragma unroll
        for (int ks = 0; ks < 2; ks++) {
            const uint32_t off = (uint32_t)(((ks << 1) | lkh) << 4);
            uint32_t a[4], b0[4], b1[4];
            LDSM4(a,  qb + (wm * 16 + lrow) * 80 + off);
            LDSM4(b0, kb + (wn * 32 + lrow) * 80 + off);
            LDSM4(b1, kb + (wn * 32 + 16 + lrow) * 80 + off);
            MMA16816(acc[0], a, b0[0], b0[2]);
            MMA16816(acc[1], a, b0[1], b0[3]);
            MMA16816(acc[2], a, b1[0], b1[2]);
            MMA16816(acc[3], a, b1[1], b1[3]);
        }
        const int tq = lane >> 2, tr = lane & 3;
        float* Ssm = (float*)(sb + OFF_S);
        #pragma unroll
        for (int nt = 0; nt < 4; nt++)
            #pragma unroll
            for (int q = 0; q < 4; q++) {
                int row = wm * 16 + tq + (q >> 1) * 8;
                int col = wn * 32 + nt * 8 + tr * 2 + (q & 1);
                Ssm[row * 68 + col] = acc[nt][q];
            }
    }
    CP_WAIT(0);
    __syncthreads();

    // ---- bias+mask add + softmax (un-normalized; inv stored per row) ----
    {
        int row = t >> 2, p = t & 3;
        bool act = row < NTOK;
        int c0 = p * 13;
        int cn = (p == 3) ? 10 : 13;                 // 13+13+13+10 = 49
        float* srow = (float*)(sb + OFF_S) + row * 68;
        const float* brow = (const float*)(sb + OFF_BM) + row * 52;
        float mx = -1e30f;
        if (act)
            for (int c = 0; c < cn; c++) {
                int m = c0 + c;
                float v = srow[m] + brow[m];
                srow[m] = v;
                mx = fmaxf(mx, v);
            }
        mx = fmaxf(mx, __shfl_xor_sync(0xffffffffu, mx, 1));
        mx = fmaxf(mx, __shfl_xor_sync(0xffffffffu, mx, 2));
        float sum = 0.f;
        if (act)
            for (int c = 0; c < cn; c++) {
                float e = __expf(srow[c0 + c] - mx);
                srow[c0 + c] = e;
                sum += e;
            }
        sum += __shfl_xor_sync(0xffffffffu, sum, 1);
        sum += __shfl_xor_sync(0xffffffffu, sum, 2);
        if (act && p == 0)
            ((float*)(sb + OFF_INV))[row] = 1.0f / sum;
    }
    __syncthreads();

    // ---- pack P = e * inv to fp16 over q/k region (zero outside 49x49) ----
    {
        const float* Ssm = (const float*)(sb + OFF_S);
        const float* inv = (const float*)(sb + OFF_INV);
        for (int i = t; i < 2048; i += ATT_T) {
            int n = i >> 5, mp = (i & 31) << 1;
            float v0 = 0.f, v1 = 0.f;
            if (n < NTOK) {
                float iv = inv[n];
                if (mp < NTOK)     v0 = Ssm[n * 68 + mp] * iv;
                if (mp + 1 < NTOK) v1 = Ssm[n * 68 + mp + 1] * iv;
            }
            __half2 hp = __floats2half2_rn(v0, v1);
            *(uint32_t*)(sb + OFF_P + n * 144 + mp * 2) = *(uint32_t*)&hp;
        }
    }
    __syncthreads();

    // ---- out = P V (64x32x64): 8 warps = 4(n) x 2(d-halves), V via trans ----
    {
        const uint32_t pb = sbu + OFF_P, vb = sbu + OFF_V;
        const int wpn = wid & 3, wd = wid >> 2;
        float acc[2][4];
        #pragma unroll
        for (int i = 0; i < 2; i++)
            #pragma unroll
            for (int q = 0; q < 4; q++) acc[i][q] = 0.f;
        #pragma unroll
        for (int ks = 0; ks < 4; ks++) {
            uint32_t a[4], bb[4];
            LDSM4(a, pb + (wpn * 16 + lrow) * 144 + (uint32_t)(((ks << 1) | lkh) << 4));
            LDSM4T(bb, vb + (ks * 16 + lrow) * 80 + (wd * 16 + lkh * 8) * 2);
            MMA16816(acc[0], a, bb[0], bb[1]);   // d-sub0: kgroups (m0-7, m8-15)
            MMA16816(acc[1], a, bb[2], bb[3]);   // d-sub1
        }
        const int tq = lane >> 2, tr = lane & 3;
        #pragma unroll
        for (int dt = 0; dt < 2; dt++)
            #pragma unroll
            for (int pr = 0; pr < 2; pr++) {
                int n = wpn * 16 + tq + pr * 8;
                if (n < NTOK) {
                    int d = wd * 16 + dt * 8 + tr * 2;
                    __half2 hv = __floats2half2_rn(acc[dt][pr * 2 + 0],
                                                   acc[dt][pr * 2 + 1]);
                    *(uint32_t*)(g_ah + ((size_t)b * NTOK + n) * DIMC + h * HD + d)
                        = *(uint32_t*)&hv;
                }
            }
    }
}

// ---------------- launch ---------------------------------------------------
extern "C" void kernel_launch(void* const* d_in, const int* in_sizes, int n_in,
                              void* d_out, int out_size)
{
    const float* x      = (const float*)d_in[0];
    const float* mask   = (const float*)d_in[1];
    const float* qkv_w  = (const float*)d_in[2];
    const float* qkv_b  = (const float*)d_in[3];
    const float* proj_w = (const float*)d_in[4];
    const float* proj_b = (const float*)d_in[5];
    const float* rpb    = (const float*)d_in[6];
    const int*   relidx = (const int*)d_in[7];
    float* out = (float*)d_out;
    (void)in_sizes; (void)n_in; (void)out_size;

    cudaFuncSetAttribute(mma_gemm<0>, cudaFuncAttributeMaxDynamicSharedMemorySize, SMEM_DYN);
    cudaFuncSetAttribute(mma_gemm<1>, cudaFuncAttributeMaxDynamicSharedMemorySize, SMEM_DYN);

    const int actBlocks = (M_TOTAL * DIMC) / (256 * 8);   // 37632

    // 1) converters + bias/mask table
    act_split<<<actBlocks, 256>>>(x);
    w_split<1><<<(1152 * 96 + 255) / 256, 256>>>(qkv_w, 1152 * 96);
    w_split<2><<<(384 * 96 + 255) / 256, 256>>>(proj_w, 384 * 96);
    bm_build<<<(NWIN * NH * NTOK * 52 + 255) / 256, 256>>>(mask, rpb, relidx);

    // 2) QKV projection (HMMA), fp16 q/k/v out, fused bias + scale + permute
    mma_gemm<0><<<dim3(1152 / 128, M_TOTAL / 128), 256, SMEM_DYN>>>(qkv_b, nullptr);

    // 3) windowed attention (HMMA QK^T + softmax + HMMA PV), fp16 out -> g_ah
    attn_kernel<<<BWIN * NH, ATT_T>>>();

    // 4) output projection (HMMA)
    mma_gemm<1><<<dim3(DIMC / 128, M_TOTAL / 128), 256, SMEM_DYN>>>(proj_b, out);
}

// round 15
// speedup vs baseline: 5.9852x; 1.4449x over previous
#include <cuda_runtime.h>
#include <cuda_fp16.h>
#include <cstdint>

#define DIMC   384
#define NH     12
#define HD     32
#define NTOK   49
#define BWIN   4096
#define NWIN   64
#define M_TOTAL (BWIN*NTOK)          // 200704
#define S3      77070336             // 4096*12*49*32  (one of q/k/v)

// ---------------- scratch (__device__ globals; no allocs allowed) -----------
__device__ __align__(16) __half g_qkv[3 * S3];               // q|k|v fp16 [s][b,h,n,d]
__device__ __align__(16) __half g_ah[(size_t)M_TOTAL * 384]; // fp16 activations (x, then attn-out)
__device__ __align__(16) __half g_wq[1152 * 384];            // qkv_w  fp16
__device__ __align__(16) __half g_wp[384 * 384];             // proj_w fp16
__device__ __align__(16) float  g_bm[NWIN * NH * NTOK * 52]; // bias+mask table

__device__ __forceinline__ uint32_t smem_u32(const void* p) {
    uint32_t a;
    asm("{ .reg .u64 t; cvta.to.shared.u64 t, %1; cvt.u32.u64 %0, t; }"
        : "=r"(a) : "l"(p));
    return a;
}

#define CP_ASYNC16(dst, src) \
    asm volatile("cp.async.cg.shared.global [%0], [%1], 16;" :: "r"(dst), "l"(src))
#define CP_COMMIT()  asm volatile("cp.async.commit_group;" ::: "memory")
#define CP_WAIT(n)   asm volatile("cp.async.wait_group %0;" :: "n"(n) : "memory")

#define LDSM4(r, addr) \
    asm volatile("ldmatrix.sync.aligned.m8n8.x4.shared.b16 {%0,%1,%2,%3}, [%4];" \
        : "=r"((r)[0]), "=r"((r)[1]), "=r"((r)[2]), "=r"((r)[3]) : "r"(addr))

#define LDSM4T(r, addr) \
    asm volatile("ldmatrix.sync.aligned.m8n8.x4.trans.shared.b16 {%0,%1,%2,%3}, [%4];" \
        : "=r"((r)[0]), "=r"((r)[1]), "=r"((r)[2]), "=r"((r)[3]) : "r"(addr))

#define MMA16816(c, a, bb0, bb1) \
    asm volatile("mma.sync.aligned.m16n8k16.row.col.f32.f16.f16.f32 " \
        "{%0,%1,%2,%3}, {%4,%5,%6,%7}, {%8,%9}, {%0,%1,%2,%3};" \
        : "+f"((c)[0]), "+f"((c)[1]), "+f"((c)[2]), "+f"((c)[3]) \
        : "r"((a)[0]), "r"((a)[1]), "r"((a)[2]), "r"((a)[3]), "r"(bb0), "r"(bb1))

// ---------------- fp32 -> fp16 converters ----------------------------------
__global__ void __launch_bounds__(256)
act_split(const float* __restrict__ src)
{
    size_t i = ((size_t)blockIdx.x * 256 + threadIdx.x) * 8;
    float4 v0 = *(const float4*)(src + i);
    float4 v1 = *(const float4*)(src + i + 4);
    __half2 h0 = __floats2half2_rn(v0.x, v0.y);
    __half2 h1 = __floats2half2_rn(v0.z, v0.w);
    __half2 h2 = __floats2half2_rn(v1.x, v1.y);
    __half2 h3 = __floats2half2_rn(v1.z, v1.w);
    uint4 o;
    o.x = *(uint32_t*)&h0; o.y = *(uint32_t*)&h1;
    o.z = *(uint32_t*)&h2; o.w = *(uint32_t*)&h3;
    *(uint4*)(g_ah + i) = o;
}

// weights fp16 (single plane). W: 1 = qkv_w, 2 = proj_w
template<int W>
__global__ void __launch_bounds__(256)
w_split(const float* __restrict__ w, int total4)
{
    int i = blockIdx.x * 256 + threadIdx.x;
    if (i >= total4) return;
    __half* dst = (W == 1) ? g_wq : g_wp;
    int e = i << 2;
    float4 v = *(const float4*)(w + e);
    __half2 h0 = __floats2half2_rn(v.x, v.y);
    __half2 h1 = __floats2half2_rn(v.z, v.w);
    *(uint2*)(dst + e) = make_uint2(*(uint32_t*)&h0, *(uint32_t*)&h1);
}

// ---------------- bias+mask table: g_bm[w][h][n][52] -----------------------
__global__ void __launch_bounds__(256)
bm_build(const float* __restrict__ mask, const float* __restrict__ rpb,
         const int* __restrict__ relidx)
{
    int i = blockIdx.x * 256 + threadIdx.x;      // over 64*12*49*52
    if (i >= NWIN * NH * NTOK * 52) return;
    int m  = i % 52;
    int r  = i / 52;                             // (w*12+h)*49 + n
    int n  = r % NTOK;
    int wh = r / NTOK;
    int h  = wh % NH;
    int w  = wh / NH;
    float v = 0.f;
    if (m < NTOK) {
        int nm = n * NTOK + m;
        v = rpb[relidx[nm] * NH + h] + mask[w * (NTOK * NTOK) + nm];
    }
    g_bm[i] = v;
}

// ---------------- HMMA GEMM: C[M,N] = Ah[M,384] * W[N,384]^T ---------------
// K = 384 (6 chunks of 64). BM=128, BN=128, BK=64 (128B rows, xor swizzle),
// 3-stage cp.async pipeline, 2 CTAs/SM. 8 warps (4 M x 2 N), warp tile 32x64.
#define STAGEB 32768
#define CHUNKS 6
#define SMEM_DYN (3 * STAGEB)

// MODE 0: QKV -> g_qkv (fp16) with bias + q-scale + [s,b,h,n,d] permute
// MODE 1: proj -> C row-major [M,384] + bias (fp32)
template<int MODE>
__global__ void __launch_bounds__(256, 2)
mma_gemm(const float* __restrict__ bias, float* __restrict__ C)
{
    extern __shared__ __align__(128) char smem[];
    const uint32_t sbase = smem_u32(smem);
    const int t    = threadIdx.x;
    const int wid  = t >> 5, lane = t & 31;
    const int bn   = blockIdx.x * 128;
    const int bm   = blockIdx.y * 128;

    const char* Ab = (const char*)g_ah + (size_t)bm * 768;
    const char* Bb = (const char*)((MODE == 0) ? g_wq : g_wp) + (size_t)bn * 768;

    auto load = [&](int c) {
        const int st = c % 3;
        const uint32_t sA = sbase + st * STAGEB;
        const uint32_t sB = sA + 16384;
        const int ko = c * 128;
        #pragma unroll
        for (int i = 0; i < 4; i++) {
            int idx = t + i * 256;
            int r = idx >> 3, sg = idx & 7;
            CP_ASYNC16(sA + r * 128 + ((sg ^ (r & 7)) << 4),
                       Ab + (size_t)r * 768 + ko + sg * 16);
        }
        #pragma unroll
        for (int i = 0; i < 4; i++) {
            int idx = t + i * 256;
            int r = idx >> 3, sg = idx & 7;
            CP_ASYNC16(sB + r * 128 + ((sg ^ (r & 7)) << 4),
                       Bb + (size_t)r * 768 + ko + sg * 16);
        }
    };

    float acc[2][8][4];
    #pragma unroll
    for (int m = 0; m < 2; m++)
        #pragma unroll
        for (int n = 0; n < 8; n++)
            #pragma unroll
            for (int q = 0; q < 4; q++) acc[m][n][q] = 0.f;

    load(0); CP_COMMIT();
    load(1); CP_COMMIT();

    const int wm = wid & 3, wn = wid >> 2;
    const int lrow = lane & 15, lkh = lane >> 4;
    const int lx = lrow & 7;               // row-dependent part of swizzle
    const int ar0 = wm * 32 + lrow, ar1 = ar0 + 16;
    const int br0 = wn * 64 + lrow;

    for (int j = 0; j < CHUNKS; j++) {
        CP_WAIT(1);
        __syncthreads();
        if (j + 2 < CHUNKS) load(j + 2);
        CP_COMMIT();

        const uint32_t sA = sbase + (j % 3) * STAGEB;
        const uint32_t sB = sA + 16384;
        #pragma unroll
        for (int ks = 0; ks < 4; ks++) {
            const int kx = (((ks << 1) | lkh) ^ lx) << 4;
            uint32_t a0[4], a1[4], b0[4], b1[4], b2[4], b3[4];
            LDSM4(a0, sA + ar0 * 128 + kx);
            LDSM4(a1, sA + ar1 * 128 + kx);
            LDSM4(b0, sB + (br0     ) * 128 + kx);
            LDSM4(b1, sB + (br0 + 16) * 128 + kx);
            LDSM4(b2, sB + (br0 + 32) * 128 + kx);
            LDSM4(b3, sB + (br0 + 48) * 128 + kx);
            MMA16816(acc[0][0], a0, b0[0], b0[2]);
            MMA16816(acc[0][1], a0, b0[1], b0[3]);
            MMA16816(acc[0][2], a0, b1[0], b1[2]);
            MMA16816(acc[0][3], a0, b1[1], b1[3]);
            MMA16816(acc[0][4], a0, b2[0], b2[2]);
            MMA16816(acc[0][5], a0, b2[1], b2[3]);
            MMA16816(acc[0][6], a0, b3[0], b3[2]);
            MMA16816(acc[0][7], a0, b3[1], b3[3]);
            MMA16816(acc[1][0], a1, b0[0], b0[2]);
            MMA16816(acc[1][1], a1, b0[1], b0[3]);
            MMA16816(acc[1][2], a1, b1[0], b1[2]);
            MMA16816(acc[1][3], a1, b1[1], b1[3]);
            MMA16816(acc[1][4], a1, b2[0], b2[2]);
            MMA16816(acc[1][5], a1, b2[1], b2[3]);
            MMA16816(acc[1][6], a1, b3[0], b3[2]);
            MMA16816(acc[1][7], a1, b3[1], b3[3]);
        }
    }

    // ---- epilogue: C frag thread map: rows +tq (+8), cols +tr*2 ----
    const int tq = lane >> 2, tr = lane & 3;
    if (MODE == 0) {
        const int s = bn / DIMC;                 // BN=128, 384%128==0 -> const
        const float scl = (s == 0) ? 0.17677669529663687f : 1.0f;
        #pragma unroll
        for (int mt = 0; mt < 2; mt++) {
            const int rb = bm + wm * 32 + mt * 16 + tq;
            #pragma unroll
            for (int pr = 0; pr < 2; pr++) {
                const int gi = rb + pr * 8;
                const int b = gi / NTOK, n = gi - b * NTOK;
                #pragma unroll
                for (int nt = 0; nt < 8; nt++) {
                    const int gj = bn + wn * 64 + nt * 8 + tr * 2;
                    const int h = (gj - s * DIMC) >> 5, d = gj & 31;
                    float2 bb = *(const float2*)(bias + gj);
                    __half2 hv = __floats2half2_rn(
                        (acc[mt][nt][pr * 2 + 0] + bb.x) * scl,
                        (acc[mt][nt][pr * 2 + 1] + bb.y) * scl);
                    *(uint32_t*)(g_qkv + (size_t)s * S3 +
                                 (((size_t)b * NH + h) * NTOK + n) * HD + d)
                        = *(uint32_t*)&hv;
                }
            }
        }
    } else {
        #pragma unroll
        for (int mt = 0; mt < 2; mt++) {
            const int rb = bm + wm * 32 + mt * 16 + tq;
            #pragma unroll
            for (int pr = 0; pr < 2; pr++) {
                const int gi = rb + pr * 8;
                #pragma unroll
                for (int nt = 0; nt < 8; nt++) {
                    const int gj = bn + wn * 64 + nt * 8 + tr * 2;
                    float2 bb = *(const float2*)(bias + gj);
                    float2 o;
                    o.x = acc[mt][nt][pr * 2 + 0] + bb.x;
                    o.y = acc[mt][nt][pr * 2 + 1] + bb.y;
                    *(float2*)(C + (size_t)gi * DIMC + gj) = o;
                }
            }
        }
    }
}

// ---------------- fused window attention, HMMA -----------------------------
// One block per (window, head). 256 threads = 8 warps.
// bm table cp.async'd during QK^T; V consumed via ldmatrix.trans (no
// explicit transpose); normalization folded into the P fp16 pack.
#define ATT_T 256
// smem offsets (bytes) in one static buffer
#define OFF_Q   0            // 64 rows * 80B
#define OFF_K   5120
#define OFF_V   10240
#define OFF_BM  15360        // 49*52 fp32 = 10192
#define OFF_S   25552        // 64*68 fp32 = 17408
#define OFF_INV 42960        // 64 fp32
#define OFF_P   0            // 64 rows * 144B = 9216 (overlays q/k after QK^T)
#define SB_SZ   43264

__global__ void __launch_bounds__(ATT_T)
attn_kernel()
{
    __shared__ __align__(16) char sb[SB_SZ];
    const uint32_t sbu = smem_u32(sb);

    const int bh = blockIdx.x;
    const int b  = bh / NH;
    const int h  = bh - b * NH;
    const int w  = b & (NWIN - 1);
    const int t  = threadIdx.x;
    const int wid = t >> 5, lane = t & 31;
    const int lrow = lane & 15, lkh = lane >> 4;

    const __half* qg = g_qkv + (size_t)bh * (NTOK * HD);
    const __half* kg = qg + S3;
    const __half* vg = qg + 2 * (size_t)S3;

    // ---- bm tile via cp.async (lands during QK^T) ----
    {
        const char* bmg = (const char*)(g_bm + (size_t)(w * NH + h) * (NTOK * 52));
        for (int i = t; i < 637; i += ATT_T)      // 49*52 floats = 637 x 16B
            CP_ASYNC16(sbu + OFF_BM + i * 16, bmg + (size_t)i * 16);
        CP_COMMIT();
    }

    // ---- stage q,k,v rows (80B stride) + zero pad rows 49..63 ----
    for (int i = t; i < 784; i += ATT_T) {        // 49*32/2 uint32s
        int n = i >> 4, dp = (i & 15) << 1;
        *(uint32_t*)(sb + OFF_Q + n * 80 + dp * 2) = ((const uint32_t*)qg)[i];
        *(uint32_t*)(sb + OFF_K + n * 80 + dp * 2) = ((const uint32_t*)kg)[i];
        *(uint32_t*)(sb + OFF_V + n * 80 + dp * 2) = ((const uint32_t*)vg)[i];
    }
    for (int i = t; i < 720; i += ATT_T) {        // 3 arrays * 15 rows * 16 u32
        int arr = i / 240, j = i % 240;
        int r = 49 + (j >> 4), dp = (j & 15) << 1;
        *(uint32_t*)(sb + arr * 5120 + r * 80 + dp * 2) = 0u;
    }
    __syncthreads();

    // ---- S = q k^T (64x64x32): 8 warps = 4(n) x 2(m-halves) ----
    {
        const uint32_t qb = sbu + OFF_Q, kb = sbu + OFF_K;
        const int wm = wid & 3, wn = wid >> 2;
        float acc[4][4];
        #pragma unroll
        for (int i = 0; i < 4; i++)
            #pragma unroll
            for (int q = 0; q < 4; q++) acc[i][q] = 0.f;
        #pragma unroll
        for (int ks = 0; ks < 2; ks++) {
            const uint32_t off = (uint32_t)(((ks << 1) | lkh) << 4);
            uint32_t a[4], b0[4], b1[4];
            LDSM4(a,  qb + (wm * 16 + lrow) * 80 + off);
            LDSM4(b0, kb + (wn * 32 + lrow) * 80 + off);
            LDSM4(b1, kb + (wn * 32 + 16 + lrow) * 80 + off);
            MMA16816(acc[0], a, b0[0], b0[2]);
            MMA16816(acc[1], a, b0[1], b0[3]);
            MMA16816(acc[2], a, b1[0], b1[2]);
            MMA16816(acc[3], a, b1[1], b1[3]);
        }
        const int tq = lane >> 2, tr = lane & 3;
        float* Ssm = (float*)(sb + OFF_S);
        #pragma unroll
        for (int nt = 0; nt < 4; nt++)
            #pragma unroll
            for (int q = 0; q < 4; q++) {
                int row = wm * 16 + tq + (q >> 1) * 8;
                int col = wn * 32 + nt * 8 + tr * 2 + (q & 1);
                Ssm[row * 68 + col] = acc[nt][q];
            }
    }
    CP_WAIT(0);
    __syncthreads();

    // ---- bias+mask add + softmax (un-normalized; inv stored per row) ----
    {
        int row = t >> 2, p = t & 3;
        bool act = row < NTOK;
        int c0 = p * 13;
        int cn = (p == 3) ? 10 : 13;                 // 13+13+13+10 = 49
        float* srow = (float*)(sb + OFF_S) + row * 68;
        const float* brow = (const float*)(sb + OFF_BM) + row * 52;
        float mx = -1e30f;
        if (act)
            for (int c = 0; c < cn; c++) {
                int m = c0 + c;
                float v = srow[m] + brow[m];
                srow[m] = v;
                mx = fmaxf(mx, v);
            }
        mx = fmaxf(mx, __shfl_xor_sync(0xffffffffu, mx, 1));
        mx = fmaxf(mx, __shfl_xor_sync(0xffffffffu, mx, 2));
        float sum = 0.f;
        if (act)
            for (int c = 0; c < cn; c++) {
                float e = __expf(srow[c0 + c] - mx);
                srow[c0 + c] = e;
                sum += e;
            }
        sum += __shfl_xor_sync(0xffffffffu, sum, 1);
        sum += __shfl_xor_sync(0xffffffffu, sum, 2);
        if (act && p == 0)
            ((float*)(sb + OFF_INV))[row] = 1.0f / sum;
    }
    __syncthreads();

    // ---- pack P = e * inv to fp16 over q/k region (zero outside 49x49) ----
    {
        const float* Ssm = (const float*)(sb + OFF_S);
        const float* inv = (const float*)(sb + OFF_INV);
        for (int i = t; i < 2048; i += ATT_T) {
            int n = i >> 5, mp = (i & 31) << 1;
            float v0 = 0.f, v1 = 0.f;
            if (n < NTOK) {
                float iv = inv[n];
                if (mp < NTOK)     v0 = Ssm[n * 68 + mp] * iv;
                if (mp + 1 < NTOK) v1 = Ssm[n * 68 + mp + 1] * iv;
            }
            __half2 hp = __floats2half2_rn(v0, v1);
            *(uint32_t*)(sb + OFF_P + n * 144 + mp * 2) = *(uint32_t*)&hp;
        }
    }
    __syncthreads();

    // ---- out = P V (64x32x64): 8 warps = 4(n) x 2(d-halves), V via trans ----
    {
        const uint32_t pb = sbu + OFF_P, vb = sbu + OFF_V;
        const int wpn = wid & 3, wd = wid >> 2;
        float acc[2][4];
        #pragma unroll
        for (int i = 0; i < 2; i++)
            #pragma unroll
            for (int q = 0; q < 4; q++) acc[i][q] = 0.f;
        #pragma unroll
        for (int ks = 0; ks < 4; ks++) {
            uint32_t a[4], bb[4];
            LDSM4(a, pb + (wpn * 16 + lrow) * 144 + (uint32_t)(((ks << 1) | lkh) << 4));
            LDSM4T(bb, vb + (ks * 16 + lrow) * 80 + (wd * 16 + lkh * 8) * 2);
            MMA16816(acc[0], a, bb[0], bb[1]);   // d-sub0: kgroups (m0-7, m8-15)
            MMA16816(acc[1], a, bb[2], bb[3]);   // d-sub1
        }
        const int tq = lane >> 2, tr = lane & 3;
        #pragma unroll
        for (int dt = 0; dt < 2; dt++)
            #pragma unroll
            for (int pr = 0; pr < 2; pr++) {
                int n = wpn * 16 + tq + pr * 8;
                if (n < NTOK) {
                    int d = wd * 16 + dt * 8 + tr * 2;
                    __half2 hv = __floats2half2_rn(acc[dt][pr * 2 + 0],
                                                   acc[dt][pr * 2 + 1]);
                    *(uint32_t*)(g_ah + ((size_t)b * NTOK + n) * DIMC + h * HD + d)
                        = *(uint32_t*)&hv;
                }
            }
    }
}

// ---------------- launch ---------------------------------------------------
extern "C" void kernel_launch(void* const* d_in, const int* in_sizes, int n_in,
                              void* d_out, int out_size)
{
    const float* x      = (const float*)d_in[0];
    const float* mask   = (const float*)d_in[1];
    const float* qkv_w  = (const float*)d_in[2];
    const float* qkv_b  = (const float*)d_in[3];
    const float* proj_w = (const float*)d_in[4];
    const float* proj_b = (const float*)d_in[5];
    const float* rpb    = (const float*)d_in[6];
    const int*   relidx = (const int*)d_in[7];
    float* out = (float*)d_out;
    (void)in_sizes; (void)n_in; (void)out_size;

    cudaFuncSetAttribute(mma_gemm<0>, cudaFuncAttributeMaxDynamicSharedMemorySize, SMEM_DYN);
    cudaFuncSetAttribute(mma_gemm<1>, cudaFuncAttributeMaxDynamicSharedMemorySize, SMEM_DYN);

    const int actBlocks = (M_TOTAL * DIMC) / (256 * 8);   // 37632

    // 1) converters + bias/mask table
    act_split<<<actBlocks, 256>>>(x);
    w_split<1><<<(1152 * 96 + 255) / 256, 256>>>(qkv_w, 1152 * 96);
    w_split<2><<<(384 * 96 + 255) / 256, 256>>>(proj_w, 384 * 96);
    bm_build<<<(NWIN * NH * NTOK * 52 + 255) / 256, 256>>>(mask, rpb, relidx);

    // 2) QKV projection (HMMA, K=384), fp16 q/k/v out, fused bias+scale+permute
    mma_gemm<0><<<dim3(1152 / 128, M_TOTAL / 128), 256, SMEM_DYN>>>(qkv_b, nullptr);

    // 3) windowed attention (HMMA QK^T + softmax + HMMA PV), fp16 out -> g_ah
    attn_kernel<<<BWIN * NH, ATT_T>>>();

    // 4) output projection (HMMA, K=384)
    mma_gemm<1><<<dim3(DIMC / 128, M_TOTAL / 128), 256, SMEM_DYN>>>(proj_b, out);
}

// round 17
// speedup vs baseline: 6.1977x; 1.0355x over previous
#include <cuda_runtime.h>
#include <cuda_fp16.h>
#include <cstdint>

#define DIMC   384
#define NH     12
#define HD     32
#define NTOK   49
#define BWIN   4096
#define NWIN   64
#define M_TOTAL (BWIN*NTOK)          // 200704
#define S3      77070336             // 4096*12*49*32  (one of q/k/v)

// ---------------- scratch (__device__ globals; no allocs allowed) -----------
__device__ __align__(16) __half g_qkv[3 * S3];               // q|k|v fp16 [s][b,h,n,d]
__device__ __align__(16) __half g_ah[(size_t)M_TOTAL * 384]; // fp16 activations (x, then attn-out)
__device__ __align__(16) __half g_wq[1152 * 384];            // qkv_w  fp16
__device__ __align__(16) __half g_wp[384 * 384];             // proj_w fp16
__device__ __align__(16) float  g_bm[NWIN * NH * NTOK * 52]; // bias+mask table

__device__ __forceinline__ uint32_t smem_u32(const void* p) {
    uint32_t a;
    asm("{ .reg .u64 t; cvta.to.shared.u64 t, %1; cvt.u32.u64 %0, t; }"
        : "=r"(a) : "l"(p));
    return a;
}

#define CP_ASYNC16(dst, src) \
    asm volatile("cp.async.cg.shared.global [%0], [%1], 16;" :: "r"(dst), "l"(src))
#define CP_COMMIT()  asm volatile("cp.async.commit_group;" ::: "memory")
#define CP_WAIT(n)   asm volatile("cp.async.wait_group %0;" :: "n"(n) : "memory")

#define LDSM4(r, addr) \
    asm volatile("ldmatrix.sync.aligned.m8n8.x4.shared.b16 {%0,%1,%2,%3}, [%4];" \
        : "=r"((r)[0]), "=r"((r)[1]), "=r"((r)[2]), "=r"((r)[3]) : "r"(addr))

#define LDSM4T(r, addr) \
    asm volatile("ldmatrix.sync.aligned.m8n8.x4.trans.shared.b16 {%0,%1,%2,%3}, [%4];" \
        : "=r"((r)[0]), "=r"((r)[1]), "=r"((r)[2]), "=r"((r)[3]) : "r"(addr))

#define MMA16816(c, a, bb0, bb1) \
    asm volatile("mma.sync.aligned.m16n8k16.row.col.f32.f16.f16.f32 " \
        "{%0,%1,%2,%3}, {%4,%5,%6,%7}, {%8,%9}, {%0,%1,%2,%3};" \
        : "+f"((c)[0]), "+f"((c)[1]), "+f"((c)[2]), "+f"((c)[3]) \
        : "r"((a)[0]), "r"((a)[1]), "r"((a)[2]), "r"((a)[3]), "r"(bb0), "r"(bb1))

// ---------------- fp32 -> fp16 converters ----------------------------------
__global__ void __launch_bounds__(256)
act_split(const float* __restrict__ src)
{
    size_t i = ((size_t)blockIdx.x * 256 + threadIdx.x) * 8;
    float4 v0 = *(const float4*)(src + i);
    float4 v1 = *(const float4*)(src + i + 4);
    __half2 h0 = __floats2half2_rn(v0.x, v0.y);
    __half2 h1 = __floats2half2_rn(v0.z, v0.w);
    __half2 h2 = __floats2half2_rn(v1.x, v1.y);
    __half2 h3 = __floats2half2_rn(v1.z, v1.w);
    uint4 o;
    o.x = *(uint32_t*)&h0; o.y = *(uint32_t*)&h1;
    o.z = *(uint32_t*)&h2; o.w = *(uint32_t*)&h3;
    *(uint4*)(g_ah + i) = o;
}

// weights fp16 (single plane). W: 1 = qkv_w, 2 = proj_w
template<int W>
__global__ void __launch_bounds__(256)
w_split(const float* __restrict__ w, int total4)
{
    int i = blockIdx.x * 256 + threadIdx.x;
    if (i >= total4) return;
    __half* dst = (W == 1) ? g_wq : g_wp;
    int e = i << 2;
    float4 v = *(const float4*)(w + e);
    __half2 h0 = __floats2half2_rn(v.x, v.y);
    __half2 h1 = __floats2half2_rn(v.z, v.w);
    *(uint2*)(dst + e) = make_uint2(*(uint32_t*)&h0, *(uint32_t*)&h1);
}

// ---------------- bias+mask table: g_bm[w][h][n][52] -----------------------
__global__ void __launch_bounds__(256)
bm_build(const float* __restrict__ mask, const float* __restrict__ rpb,
         const int* __restrict__ relidx)
{
    int i = blockIdx.x * 256 + threadIdx.x;      // over 64*12*49*52
    if (i >= NWIN * NH * NTOK * 52) return;
    int m  = i % 52;
    int r  = i / 52;                             // (w*12+h)*49 + n
    int n  = r % NTOK;
    int wh = r / NTOK;
    int h  = wh % NH;
    int w  = wh / NH;
    float v = 0.f;
    if (m < NTOK) {
        int nm = n * NTOK + m;
        v = rpb[relidx[nm] * NH + h] + mask[w * (NTOK * NTOK) + nm];
    }
    g_bm[i] = v;
}

// ---------------- HMMA GEMM: C[M,N] = Ah[M,384] * W[N,384]^T ---------------
// K = 384 (6 chunks of 64). BM=128, BN=128, BK=64 (128B rows, xor swizzle),
// 3-stage cp.async pipeline, 2 CTAs/SM. 8 warps (4 M x 2 N), warp tile 32x64.
#define STAGEB 32768
#define CHUNKS 6
#define SMEM_DYN (3 * STAGEB)

// MODE 0: QKV -> g_qkv (fp16) with bias + q-scale + [s,b,h,n,d] permute
// MODE 1: proj -> C row-major [M,384] + bias (fp32)
template<int MODE>
__global__ void __launch_bounds__(256, 2)
mma_gemm(const float* __restrict__ bias, float* __restrict__ C)
{
    extern __shared__ __align__(128) char smem[];
    const uint32_t sbase = smem_u32(smem);
    const int t    = threadIdx.x;
    const int wid  = t >> 5, lane = t & 31;
    const int bn   = blockIdx.x * 128;
    const int bm   = blockIdx.y * 128;

    const char* Ab = (const char*)g_ah + (size_t)bm * 768;
    const char* Bb = (const char*)((MODE == 0) ? g_wq : g_wp) + (size_t)bn * 768;

    auto load = [&](int c) {
        const int st = c % 3;
        const uint32_t sA = sbase + st * STAGEB;
        const uint32_t sB = sA + 16384;
        const int ko = c * 128;
        #pragma unroll
        for (int i = 0; i < 4; i++) {
            int idx = t + i * 256;
            int r = idx >> 3, sg = idx & 7;
            CP_ASYNC16(sA + r * 128 + ((sg ^ (r & 7)) << 4),
                       Ab + (size_t)r * 768 + ko + sg * 16);
        }
        #pragma unroll
        for (int i = 0; i < 4; i++) {
            int idx = t + i * 256;
            int r = idx >> 3, sg = idx & 7;
            CP_ASYNC16(sB + r * 128 + ((sg ^ (r & 7)) << 4),
                       Bb + (size_t)r * 768 + ko + sg * 16);
        }
    };

    float acc[2][8][4];
    #pragma unroll
    for (int m = 0; m < 2; m++)
        #pragma unroll
        for (int n = 0; n < 8; n++)
            #pragma unroll
            for (int q = 0; q < 4; q++) acc[m][n][q] = 0.f;

    load(0); CP_COMMIT();
    load(1); CP_COMMIT();

    const int wm = wid & 3, wn = wid >> 2;
    const int lrow = lane & 15, lkh = lane >> 4;
    const int lx = lrow & 7;               // row-dependent part of swizzle
    const int ar0 = wm * 32 + lrow, ar1 = ar0 + 16;
    const int br0 = wn * 64 + lrow;

    for (int j = 0; j < CHUNKS; j++) {
        CP_WAIT(1);
        __syncthreads();
        if (j + 2 < CHUNKS) load(j + 2);
        CP_COMMIT();

        const uint32_t sA = sbase + (j % 3) * STAGEB;
        const uint32_t sB = sA + 16384;
        #pragma unroll
        for (int ks = 0; ks < 4; ks++) {
            const int kx = (((ks << 1) | lkh) ^ lx) << 4;
            uint32_t a0[4], a1[4], b0[4], b1[4], b2[4], b3[4];
            LDSM4(a0, sA + ar0 * 128 + kx);
            LDSM4(a1, sA + ar1 * 128 + kx);
            LDSM4(b0, sB + (br0     ) * 128 + kx);
            LDSM4(b1, sB + (br0 + 16) * 128 + kx);
            LDSM4(b2, sB + (br0 + 32) * 128 + kx);
            LDSM4(b3, sB + (br0 + 48) * 128 + kx);
            MMA16816(acc[0][0], a0, b0[0], b0[2]);
            MMA16816(acc[0][1], a0, b0[1], b0[3]);
            MMA16816(acc[0][2], a0, b1[0], b1[2]);
            MMA16816(acc[0][3], a0, b1[1], b1[3]);
            MMA16816(acc[0][4], a0, b2[0], b2[2]);
            MMA16816(acc[0][5], a0, b2[1], b2[3]);
            MMA16816(acc[0][6], a0, b3[0], b3[2]);
            MMA16816(acc[0][7], a0, b3[1], b3[3]);
            MMA16816(acc[1][0], a1, b0[0], b0[2]);
            MMA16816(acc[1][1], a1, b0[1], b0[3]);
            MMA16816(acc[1][2], a1, b1[0], b1[2]);
            MMA16816(acc[1][3], a1, b1[1], b1[3]);
            MMA16816(acc[1][4], a1, b2[0], b2[2]);
            MMA16816(acc[1][5], a1, b2[1], b2[3]);
            MMA16816(acc[1][6], a1, b3[0], b3[2]);
            MMA16816(acc[1][7], a1, b3[1], b3[3]);
        }
    }

    // ---- epilogue: C frag thread map: rows +tq (+8), cols +tr*2 ----
    const int tq = lane >> 2, tr = lane & 3;
    if (MODE == 0) {
        const int s = bn / DIMC;                 // BN=128, 384%128==0 -> const
        const float scl = (s == 0) ? 0.17677669529663687f : 1.0f;
        #pragma unroll
        for (int mt = 0; mt < 2; mt++) {
            const int rb = bm + wm * 32 + mt * 16 + tq;
            #pragma unroll
            for (int pr = 0; pr < 2; pr++) {
                const int gi = rb + pr * 8;
                const int b = gi / NTOK, n = gi - b * NTOK;
                #pragma unroll
                for (int nt = 0; nt < 8; nt++) {
                    const int gj = bn + wn * 64 + nt * 8 + tr * 2;
                    const int h = (gj - s * DIMC) >> 5, d = gj & 31;
                    float2 bb = *(const float2*)(bias + gj);
                    __half2 hv = __floats2half2_rn(
                        (acc[mt][nt][pr * 2 + 0] + bb.x) * scl,
                        (acc[mt][nt][pr * 2 + 1] + bb.y) * scl);
                    *(uint32_t*)(g_qkv + (size_t)s * S3 +
                                 (((size_t)b * NH + h) * NTOK + n) * HD + d)
                        = *(uint32_t*)&hv;
                }
            }
        }
    } else {
        #pragma unroll
        for (int mt = 0; mt < 2; mt++) {
            const int rb = bm + wm * 32 + mt * 16 + tq;
            #pragma unroll
            for (int pr = 0; pr < 2; pr++) {
                const int gi = rb + pr * 8;
                #pragma unroll
                for (int nt = 0; nt < 8; nt++) {
                    const int gj = bn + wn * 64 + nt * 8 + tr * 2;
                    float2 bb = *(const float2*)(bias + gj);
                    float2 o;
                    o.x = acc[mt][nt][pr * 2 + 0] + bb.x;
                    o.y = acc[mt][nt][pr * 2 + 1] + bb.y;
                    *(float2*)(C + (size_t)gi * DIMC + gj) = o;
                }
            }
        }
    }
}

// ---------------- fused window attention, HMMA -----------------------------
// One block per (window, head). 256 threads = 8 warps.
// bm table cp.async'd during QK^T; V via ldmatrix.trans; softmax exp in
// fp16x2 (h2exp2) written straight into P (un-normalized); normalization
// deferred to the PV epilogue (PV is linear). 3 barriers total.
#define ATT_T 256
// smem offsets (bytes) in one static buffer
#define OFF_Q   0            // 64 rows * 80B
#define OFF_K   5120
#define OFF_V   10240
#define OFF_BM  15360        // 49*52 fp32 = 10192
#define OFF_S   25552        // 64*68 fp32 = 17408
#define OFF_INV 42960        // 64 fp32
#define OFF_P   0            // 64 rows * 144B = 9216 (overlays q/k after QK^T)
#define SB_SZ   43264

__global__ void __launch_bounds__(ATT_T)
attn_kernel()
{
    __shared__ __align__(16) char sb[SB_SZ];
    const uint32_t sbu = smem_u32(sb);

    const int bh = blockIdx.x;
    const int b  = bh / NH;
    const int h  = bh - b * NH;
    const int w  = b & (NWIN - 1);
    const int t  = threadIdx.x;
    const int wid = t >> 5, lane = t & 31;
    const int lrow = lane & 15, lkh = lane >> 4;

    const __half* qg = g_qkv + (size_t)bh * (NTOK * HD);
    const __half* kg = qg + S3;
    const __half* vg = qg + 2 * (size_t)S3;

    // ---- bm tile via cp.async (lands during QK^T) ----
    {
        const char* bmg = (const char*)(g_bm + (size_t)(w * NH + h) * (NTOK * 52));
        for (int i = t; i < 637; i += ATT_T)      // 49*52 floats = 637 x 16B
            CP_ASYNC16(sbu + OFF_BM + i * 16, bmg + (size_t)i * 16);
        CP_COMMIT();
    }

    // ---- stage q,k,v rows (80B stride) + zero pad rows 49..63 ----
    for (int i = t; i < 784; i += ATT_T) {        // 49*32/2 uint32s
        int n = i >> 4, dp = (i & 15) << 1;
        *(uint32_t*)(sb + OFF_Q + n * 80 + dp * 2) = ((const uint32_t*)qg)[i];
        *(uint32_t*)(sb + OFF_K + n * 80 + dp * 2) = ((const uint32_t*)kg)[i];
        *(uint32_t*)(sb + OFF_V + n * 80 + dp * 2) = ((const uint32_t*)vg)[i];
    }
    for (int i = t; i < 720; i += ATT_T) {        // 3 arrays * 15 rows * 16 u32
        int arr = i / 240, j = i % 240;
        int r = 49 + (j >> 4), dp = (j & 15) << 1;
        *(uint32_t*)(sb + arr * 5120 + r * 80 + dp * 2) = 0u;
    }
    __syncthreads();

    // ---- S = q k^T (64x64x32): 8 warps = 4(n) x 2(m-halves) ----
    {
        const uint32_t qb = sbu + OFF_Q, kb = sbu + OFF_K;
        const int wm = wid & 3, wn = wid >> 2;
        float acc[4][4];
        #pragma unroll
        for (int i = 0; i < 4; i++)
            #pragma unroll
            for (int q = 0; q < 4; q++) acc[i][q] = 0.f;
        #pragma unroll
        for (int ks = 0; ks < 2; ks++) {
            const uint32_t off = (uint32_t)(((ks << 1) | lkh) << 4);
            uint32_t a[4], b0[4], b1[4];
            LDSM4(a,  qb + (wm * 16 + lrow) * 80 + off);
            LDSM4(b0, kb + (wn * 32 + lrow) * 80 + off);
            LDSM4(b1, kb + (wn * 32 + 16 + lrow) * 80 + off);
            MMA16816(acc[0], a, b0[0], b0[2]);
            MMA16816(acc[1], a, b0[1], b0[3]);
            MMA16816(acc[2], a, b1[0], b1[2]);
            MMA16816(acc[3], a, b1[1], b1[3]);
        }
        const int tq = lane >> 2, tr = lane & 3;
        float* Ssm = (float*)(sb + OFF_S);
        #pragma unroll
        for (int nt = 0; nt < 4; nt++)
            #pragma unroll
            for (int q = 0; q < 4; q++) {
                int row = wm * 16 + tq + (q >> 1) * 8;
                int col = wn * 32 + nt * 8 + tr * 2 + (q & 1);
                Ssm[row * 68 + col] = acc[nt][q];
            }
    }
    CP_WAIT(0);
    __syncthreads();

    // ---- fused softmax: bias+max (fp32), exp in fp16x2 -> P, sum -> inv ----
    {
        const int row = t >> 2, p = t & 3;
        const bool act = row < NTOK;
        float* srow = (float*)(sb + OFF_S) + row * 68;
        const float* brow = (const float*)(sb + OFF_BM) + row * 52;
        float mx = -1e30f;
        if (act) {
            const int c0 = p * 13;
            const int cn = (p == 3) ? 10 : 13;       // 13+13+13+10 = 49
            for (int c = 0; c < cn; c++) {
                int m = c0 + c;
                float v = srow[m] + brow[m];
                srow[m] = v;
                mx = fmaxf(mx, v);
            }
            for (int c = 49 + p; c < 64; c += 4)     // pads -> exact-0 exp
                srow[c] = -1e30f;
        }
        mx = fmaxf(mx, __shfl_xor_sync(0xffffffffu, mx, 1));
        mx = fmaxf(mx, __shfl_xor_sync(0xffffffffu, mx, 2));
        __syncwarp();                                // S row visible to group

        __half2* prow = (__half2*)(sb + OFF_P + row * 144);
        float sum = 0.f;
        if (act) {
            const float L2E = 1.4426950408889634f;
            #pragma unroll
            for (int j = 0; j < 8; j++) {
                int pj = p + j * 4;                  // pairs 0..31 (cols 0..63)
                float2 v = *(float2*)(srow + 2 * pj);
                __half2 e = h2exp2(__floats2half2_rn((v.x - mx) * L2E,
                                                     (v.y - mx) * L2E));
                prow[pj] = e;
                float2 f = __half22float2(e);
                sum += f.x + f.y;                    // pads contribute +0
            }
        } else {
            const __half2 z = __half2half2(__float2half(0.f));
            #pragma unroll
            for (int j = 0; j < 8; j++)
                prow[p + j * 4] = z;
        }
        sum += __shfl_xor_sync(0xffffffffu, sum, 1);
        sum += __shfl_xor_sync(0xffffffffu, sum, 2);
        if (act && p == 0)
            ((float*)(sb + OFF_INV))[row] = 1.0f / sum;
    }
    __syncthreads();

    // ---- out = (P V) * inv[n] (64x32x64): 8 warps = 4(n) x 2(d-halves) ----
    {
        const uint32_t pb = sbu + OFF_P, vb = sbu + OFF_V;
        const float* invp = (const float*)(sb + OFF_INV);
        const int wpn = wid & 3, wd = wid >> 2;
        float acc[2][4];
        #pragma unroll
        for (int i = 0; i < 2; i++)
            #pragma unroll
            for (int q = 0; q < 4; q++) acc[i][q] = 0.f;
        #pragma unroll
        for (int ks = 0; ks < 4; ks++) {
            uint32_t a[4], bb[4];
            LDSM4(a, pb + (wpn * 16 + lrow) * 144 + (uint32_t)(((ks << 1) | lkh) << 4));
            LDSM4T(bb, vb + (ks * 16 + lrow) * 80 + (wd * 16 + lkh * 8) * 2);
            MMA16816(acc[0], a, bb[0], bb[1]);   // d-sub0: kgroups (m0-7, m8-15)
            MMA16816(acc[1], a, bb[2], bb[3]);   // d-sub1
        }
        const int tq = lane >> 2, tr = lane & 3;
        #pragma unroll
        for (int dt = 0; dt < 2; dt++)
            #pragma unroll
            for (int pr = 0; pr < 2; pr++) {
                int n = wpn * 16 + tq + pr * 8;
                if (n < NTOK) {
                    float iv = invp[n];
                    int d = wd * 16 + dt * 8 + tr * 2;
                    __half2 hv = __floats2half2_rn(acc[dt][pr * 2 + 0] * iv,
                                                   acc[dt][pr * 2 + 1] * iv);
                    *(uint32_t*)(g_ah + ((size_t)b * NTOK + n) * DIMC + h * HD + d)
                        = *(uint32_t*)&hv;
                }
            }
    }
}

// ---------------- launch ---------------------------------------------------
extern "C" void kernel_launch(void* const* d_in, const int* in_sizes, int n_in,
                              void* d_out, int out_size)
{
    const float* x      = (const float*)d_in[0];
    const float* mask   = (const float*)d_in[1];
    const float* qkv_w  = (const float*)d_in[2];
    const float* qkv_b  = (const float*)d_in[3];
    const float* proj_w = (const float*)d_in[4];
    const float* proj_b = (const float*)d_in[5];
    const float* rpb    = (const float*)d_in[6];
    const int*   relidx = (const int*)d_in[7];
    float* out = (float*)d_out;
    (void)in_sizes; (void)n_in; (void)out_size;

    cudaFuncSetAttribute(mma_gemm<0>, cudaFuncAttributeMaxDynamicSharedMemorySize, SMEM_DYN);
    cudaFuncSetAttribute(mma_gemm<1>, cudaFuncAttributeMaxDynamicSharedMemorySize, SMEM_DYN);

    const int actBlocks = (M_TOTAL * DIMC) / (256 * 8);   // 37632

    // 1) converters + bias/mask table
    act_split<<<actBlocks, 256>>>(x);
    w_split<1><<<(1152 * 96 + 255) / 256, 256>>>(qkv_w, 1152 * 96);
    w_split<2><<<(384 * 96 + 255) / 256, 256>>>(proj_w, 384 * 96);
    bm_build<<<(NWIN * NH * NTOK * 52 + 255) / 256, 256>>>(mask, rpb, relidx);

    // 2) QKV projection (HMMA, K=384), fp16 q/k/v out, fused bias+scale+permute
    mma_gemm<0><<<dim3(1152 / 128, M_TOTAL / 128), 256, SMEM_DYN>>>(qkv_b, nullptr);

    // 3) windowed attention (HMMA + fp16x2 softmax), fp16 out -> g_ah
    attn_kernel<<<BWIN * NH, ATT_T>>>();

    // 4) output projection (HMMA, K=384)
    mma_gemm<1><<<dim3(DIMC / 128, M_TOTAL / 128), 256, SMEM_DYN>>>(proj_b, out);
}